// round 14
// baseline (speedup 1.0000x reference)
#include <cuda_runtime.h>
#include <cuda_bf16.h>
#include <math.h>
#include <stdint.h>

#define B_SZ   512
#define T_SZ   128
#define HID    1024
#define EMB    512
#define GATES  4096
#define WK     1024      // recurrent K (h only)
#define NCH    16        // chunks of 64 K-elems
#define NTHR   1024

// ---------------- device scratch (allocation-free) ----------------
__device__ __nv_bfloat16 g_Whi[GATES * WK];      // [p][k'] permuted N-major (h part)
__device__ __nv_bfloat16 g_Wlo[GATES * WK];
__device__ __nv_bfloat16 g_Hhi[HID * WK];        // W_hid split, N-major [n][k]
__device__ __nv_bfloat16 g_Hlo[HID * WK];
__device__ float g_Ep[1024 * GATES];             // E'[vocab][p]: emb@Wx + b (+1 on f)
__device__ __nv_bfloat16 g_hbhi[2][B_SZ * HID];  // double-buffered h (bf16 hi/lo)
__device__ __nv_bfloat16 g_hblo[2][B_SZ * HID];
__device__ unsigned g_bar[128];                  // 4 m-group barriers, stride 32

// ---------------- helpers ----------------
__device__ __forceinline__ uint32_t smem_u32(const void* p) {
    uint32_t r;
    asm("{ .reg .u64 t; cvta.to.shared.u64 t, %1; cvt.u32.u64 %0, t; }" : "=r"(r) : "l"(p));
    return r;
}
__device__ __forceinline__ void cpa16(uint32_t dst, const void* src) {
    asm volatile("cp.async.cg.shared.global [%0], [%1], 16;" :: "r"(dst), "l"(src) : "memory");
}
#define CP_COMMIT() asm volatile("cp.async.commit_group;" ::: "memory")
#define CP_WAIT1()  asm volatile("cp.async.wait_group 1;" ::: "memory")
#define CP_WAIT0()  asm volatile("cp.async.wait_group 0;" ::: "memory")

#define LDMX4(r, addr) \
    asm volatile("ldmatrix.sync.aligned.m8n8.x4.shared.b16 {%0,%1,%2,%3}, [%4];" \
        : "=r"((r)[0]), "=r"((r)[1]), "=r"((r)[2]), "=r"((r)[3]) : "r"(addr))

#define MMA(acc, a, b0, b1) \
    asm volatile("mma.sync.aligned.m16n8k16.row.col.f32.bf16.bf16.f32 " \
        "{%0,%1,%2,%3}, {%4,%5,%6,%7}, {%8,%9}, {%0,%1,%2,%3};" \
        : "+f"((acc)[0]), "+f"((acc)[1]), "+f"((acc)[2]), "+f"((acc)[3]) \
        : "r"((a)[0]), "r"((a)[1]), "r"((a)[2]), "r"((a)[3]), "r"(b0), "r"(b1))

#define SW(o) ((uint32_t)(o) ^ ((((uint32_t)(o)) >> 3) & 0x70))

__device__ __forceinline__ float sigm(float x) { return 1.0f / (1.0f + __expf(-x)); }
__device__ __forceinline__ float tanh_f(float x) {
    float e = __expf(2.0f * x);
    return 1.0f - 2.0f / (e + 1.0f);
}

// smem: 3 stages; each stage = 4 regions (Ahi/Alo/Bhi/Blo) of 128 rows x 128B.
// smC overlaps slot 1 — disjoint from slot0/slot2 B regions (pre-barrier prefetch).
#define OFF_AHI   0
#define OFF_ALO   16384
#define OFF_BHI   32768
#define OFF_BLO   49152
#define STAGE_SZ  65536
#define STEP_SMEM (3 * STAGE_SZ)   // 196608

#define PREF_A(base, kb) do { \
    cpa16((base) + OFF_AHI + sw0, aHhi + (kb) + go0); \
    cpa16((base) + OFF_ALO + sw0, aHlo + (kb) + go0); \
} while (0)
#define PREF_B(base, kb) do { \
    cpa16((base) + OFF_BHI + sw0, bWhi + (kb) + go0); \
    cpa16((base) + OFF_BLO + sw0, bWlo + (kb) + go0); \
} while (0)

// ---------------- in-kernel images projection (16 extra CTAs) ----------------
__device__ void proj_images(char* smem, const float* __restrict__ A,
                            const float* __restrict__ W, const float* __restrict__ bias,
                            float* __restrict__ C, int pm, int pn, int tid)
{
    const int K = 2048, N = 1024;
    float (*As)[16][132] = (float(*)[16][132])smem;
    float (*Bs)[16][256] = (float(*)[16][256])(smem + 18432);

    const int ar = tid >> 3, ak = (tid & 7) * 2;
    const int br = tid >> 6, bc = (tid & 63) * 4;
    const int tm = (tid >> 5) * 4, tn = (tid & 31) * 8;

    const float* aP = A + (size_t)(pm + ar) * K + ak;
    const float* bP = W + (size_t)br * N + pn + bc;

    float acc[4][8];
    #pragma unroll
    for (int i = 0; i < 4; i++)
        #pragma unroll
        for (int j = 0; j < 8; j++) acc[i][j] = 0.0f;

    {
        const float2 va = *(const float2*)aP;
        const float4 vb = *(const float4*)bP;
        As[0][ak][ar] = va.x; As[0][ak + 1][ar] = va.y;
        *(float4*)&Bs[0][br][bc] = vb;
    }
    __syncthreads();

    int buf = 0;
    for (int k0 = 16; k0 <= K; k0 += 16) {
        const bool more = (k0 < K);
        float2 nva; float4 nvb;
        if (more) {
            nva = *(const float2*)(aP + k0);
            nvb = *(const float4*)(bP + (size_t)k0 * N);
        }
        #pragma unroll
        for (int kk = 0; kk < 16; kk++) {
            float a[4], b[8];
            *(float4*)&a[0] = *(const float4*)&As[buf][kk][tm];
            *(float4*)&b[0] = *(const float4*)&Bs[buf][kk][tn];
            *(float4*)&b[4] = *(const float4*)&Bs[buf][kk][tn + 4];
            #pragma unroll
            for (int i = 0; i < 4; i++)
                #pragma unroll
                for (int j = 0; j < 8; j++)
                    acc[i][j] = fmaf(a[i], b[j], acc[i][j]);
        }
        if (more) {
            const int nb = buf ^ 1;
            As[nb][ak][ar] = nva.x; As[nb][ak + 1][ar] = nva.y;
            *(float4*)&Bs[nb][br][bc] = nvb;
        }
        __syncthreads();
        buf ^= 1;
    }

    float bia[8];
    *(float4*)&bia[0] = *(const float4*)(bias + pn + tn);
    *(float4*)&bia[4] = *(const float4*)(bias + pn + tn + 4);
    #pragma unroll
    for (int i = 0; i < 4; i++) {
        float4 o0, o1;
        o0.x = acc[i][0] + bia[0]; o0.y = acc[i][1] + bia[1];
        o0.z = acc[i][2] + bia[2]; o0.w = acc[i][3] + bia[3];
        o1.x = acc[i][4] + bia[4]; o1.y = acc[i][5] + bia[5];
        o1.z = acc[i][6] + bia[6]; o1.w = acc[i][7] + bia[7];
        float* crow_ = C + (size_t)(pm + tm + i) * N + pn + tn;
        *(float4*)(crow_)     = o0;
        *(float4*)(crow_ + 4) = o1;
    }
}

// ==== persistent LSTM (128 steps) + fused hidden projection (step 128) + images proj ====
__global__ void __launch_bounds__(NTHR, 1)
lstm_persist(const int* __restrict__ message,
             const float* __restrict__ images, const float* __restrict__ W_img,
             const float* __restrict__ b_img, const float* __restrict__ b_hid,
             float* __restrict__ out)
{
    extern __shared__ __align__(1024) char smem[];
    const int tid = threadIdx.x;

    // ---- extra CTAs (bx >= 32): images projection on otherwise-idle SMs ----
    if (blockIdx.x >= 32) {
        const int id = (blockIdx.x - 32) * 4 + blockIdx.y;
        proj_images(smem, images, W_img, b_img, out,
                    (id >> 2) * 128, (id & 3) * 256, tid);
        return;
    }

    const uint32_t sm = smem_u32(smem);
    const int lane = tid & 31;
    const int wid  = tid >> 5;              // 0..31
    const int bx   = blockIdx.x;            // n-tile 0..31 (permuted cols)
    const int bm   = blockIdx.y * 128;      // m-tile base row

    // ---- loader addressing: 1024 threads, 1 row + 1 quarter each ----
    const int r = tid >> 3;
    const int q = tid & 7;
    const char* bWhi = (const char*)(g_Whi + (size_t)(bx * 128 + r) * WK);
    const char* bWlo = (const char*)(g_Wlo + (size_t)(bx * 128 + r) * WK);
    const char* hHi[2] = { (const char*)(g_hbhi[0] + (size_t)(bm + r) * HID),
                           (const char*)(g_hbhi[1] + (size_t)(bm + r) * HID) };
    const char* hLo[2] = { (const char*)(g_hblo[0] + (size_t)(bm + r) * HID),
                           (const char*)(g_hblo[1] + (size_t)(bm + r) * HID) };
    const uint32_t sw0 = SW(r * 128 + q * 16);
    const int go0 = q * 16;

    // ---- warp compute layout: 4(M) x 8(N) warps; warp tile 32x16 ----
    const int wm = (wid >> 3) * 32;
    const int wn = (wid & 7) * 16;
    const int aRow = (lane & 15);
    const int aSel = ((lane >> 4) & 1) * 16;
    const int bRowBase = (lane & 7) + ((lane >> 4) & 1) * 8;
    const int bSel = ((lane >> 3) & 1) * 16;

    // ---- epilogue addressing ----
    const int erow  = bm + (tid >> 3);
    const int esub  = tid & 7;
    const int* msgp = message + erow * T_SZ;
    float* smC = (float*)(smem + STAGE_SZ);

    float4 creg = make_float4(0.0f, 0.0f, 0.0f, 0.0f);

    // ---- initial pre-barrier weight prefetch (chunks 0 and 2; W only) ----
    PREF_B(sm, 0);
    PREF_B(sm + 2 * STAGE_SZ, 2 * 128);

    #pragma unroll 1
    for (int t = 0; t <= T_SZ; t++) {
        // step T_SZ is the hidden projection: only bx<8 CTAs participate
        if (t == T_SZ && bx >= 8) return;

        const int msg = (t < T_SZ) ? msgp[t] : 0;
        const char* aHhi = hHi[t & 1];
        const char* aHlo = hLo[t & 1];

        float acc[2][2][4];
        #pragma unroll
        for (int i = 0; i < 2; i++)
            #pragma unroll
            for (int j = 0; j < 2; j++)
                #pragma unroll
                for (int k = 0; k < 4; k++) acc[i][j][k] = 0.0f;

        PREF_A(sm, 0);
        CP_COMMIT();
        PREF_A(sm + STAGE_SZ, 128);
        PREF_B(sm + STAGE_SZ, 128);
        CP_COMMIT();

        int sc = 0, sp = 2;
        #pragma unroll 1
        for (int c = 0; c < NCH; c++) {
            if (c < NCH - 1) { CP_WAIT1(); } else { CP_WAIT0(); }
            __syncthreads();

            if (c + 2 < NCH) {
                const uint32_t dst = sm + sp * STAGE_SZ;
                const int kb = (c + 2) * 128;
                PREF_A(dst, kb);
                if (c != 0) PREF_B(dst, kb);
                CP_COMMIT();
            }

            const uint32_t stage = sm + sc * STAGE_SZ;
            #pragma unroll
            for (int k16 = 0; k16 < 4; k16++) {
                const int kb = k16 * 32;
                uint32_t ah[2][4], al[2][4], bh[4], bl[4];
                #pragma unroll
                for (int mi = 0; mi < 2; mi++) {
                    const uint32_t ao = SW((wm + mi * 16 + aRow) * 128 + kb + aSel);
                    LDMX4(ah[mi], stage + OFF_AHI + ao);
                    LDMX4(al[mi], stage + OFF_ALO + ao);
                }
                {
                    const uint32_t bo = SW((wn + bRowBase) * 128 + kb + bSel);
                    LDMX4(bh, stage + OFF_BHI + bo);
                    LDMX4(bl, stage + OFF_BLO + bo);
                }
                #pragma unroll
                for (int mi = 0; mi < 2; mi++) {
                    #pragma unroll
                    for (int n8 = 0; n8 < 2; n8++) {
                        const uint32_t bh0 = bh[n8 * 2], bh1 = bh[n8 * 2 + 1];
                        const uint32_t bl0 = bl[n8 * 2], bl1 = bl[n8 * 2 + 1];
                        MMA(acc[mi][n8], ah[mi], bh0, bh1);
                        MMA(acc[mi][n8], al[mi], bh0, bh1);
                        MMA(acc[mi][n8], ah[mi], bl0, bl1);
                    }
                }
            }
            sc = (sc == 2) ? 0 : sc + 1;
            sp = (sp == 2) ? 0 : sp + 1;
        }

        __syncthreads();   // all warps done with all stage slots

        // ---- pre-barrier weight prefetch for NEXT step ----
        if (t + 1 < T_SZ) {
            PREF_B(sm, 0);
            PREF_B(sm + 2 * STAGE_SZ, 2 * 128);
        } else if (t + 1 == T_SZ && bx < 8) {
            // switch to hidden-projection weights for step 128
            bWhi = (const char*)(g_Hhi + (size_t)(bx * 128 + r) * WK);
            bWlo = (const char*)(g_Hlo + (size_t)(bx * 128 + r) * WK);
            PREF_B(sm, 0);
            PREF_B(sm + 2 * STAGE_SZ, 2 * 128);
        }

        // ---- stage accumulators to smC (fp32, stride 132) ----
        #pragma unroll
        for (int mi = 0; mi < 2; mi++) {
            #pragma unroll
            for (int n8 = 0; n8 < 2; n8++) {
                const int row = wm + mi * 16 + (lane >> 2);
                const int col = wn + n8 * 8 + (lane & 3) * 2;
                smC[row * 132 + col]           = acc[mi][n8][0];
                smC[row * 132 + col + 1]       = acc[mi][n8][1];
                smC[(row + 8) * 132 + col]     = acc[mi][n8][2];
                smC[(row + 8) * 132 + col + 1] = acc[mi][n8][3];
            }
        }
        __syncthreads();

        if (t < T_SZ) {
            // ---- fused LSTM epilogue: 8 threads per row, 4 elems; c in registers ----
            const float* cr = smC + (tid >> 3) * 132 + esub * 4;
            const float* ep = g_Ep + (size_t)msg * GATES + bx * 128 + esub * 4;
            __nv_bfloat16* hh = g_hbhi[(t + 1) & 1] + (size_t)erow * HID + bx * 32 + esub * 4;
            __nv_bfloat16* hl = g_hblo[(t + 1) & 1] + (size_t)erow * HID + bx * 32 + esub * 4;
            float* cv = (float*)&creg;
            __nv_bfloat16 hhb[4], hlb[4];
            #pragma unroll
            for (int l = 0; l < 4; l++) {
                const float iv = cr[l]      + ep[l];
                const float gv = cr[32 + l] + ep[32 + l];
                const float fv = cr[64 + l] + ep[64 + l];   // +1 folded
                const float ov = cr[96 + l] + ep[96 + l];
                const float cc = sigm(fv) * cv[l] + sigm(iv) * tanh_f(gv);
                const float hv = sigm(ov) * tanh_f(cc);
                cv[l] = cc;
                const __nv_bfloat16 hi = __float2bfloat16(hv);
                hhb[l] = hi;
                hlb[l] = __float2bfloat16(hv - __bfloat162float(hi));
            }
            *(int2*)hh = *(int2*)hhb;
            *(int2*)hl = *(int2*)hlb;
        } else {
            // ---- hidden-projection epilogue: bias + store 128 cols per CTA ----
            const float* cr = smC + (tid >> 3) * 132 + esub * 16;
            const int gcol = bx * 128 + esub * 16;
            float* o2 = out + (size_t)B_SZ * HID + (size_t)erow * 1024 + gcol;
            #pragma unroll
            for (int j = 0; j < 4; j++) {
                float4 v = *(const float4*)(cr + j * 4);
                const float4 b = *(const float4*)(b_hid + gcol + j * 4);
                v.x += b.x; v.y += b.y; v.z += b.z; v.w += b.w;
                *(float4*)(o2 + j * 4) = v;
            }
        }

        // ---- per-m-group barrier (32 CTAs sharing this bm), rounds 1..128 ----
        if (t < T_SZ) {
            __threadfence();
            __syncthreads();
            if (tid == 0) {
                unsigned* bar = g_bar + (blockIdx.y << 5);
                atomicAdd(bar, 1u);
                const unsigned target = 32u * (unsigned)(t + 1);
                while (*(volatile unsigned*)bar < target) { __nanosleep(64); }
            }
            __syncthreads();
        }
    }
}

// ====== prep: coalesced tiled transpose + bf16 split for W_cell(h) and W_hid ======
// grid (16, 64, 2): z=0 -> W_cell rows 512..1535 with gate permutation; z=1 -> W_hid (y<16)
__global__ __launch_bounds__(256)
void prep_w2(const float* __restrict__ Wc, const float* __restrict__ Wh)
{
    __shared__ float tile[64][65];
    const int tid = threadIdx.x;
    const int isH = blockIdx.z;
    if (isH && blockIdx.y >= 16) return;
    const int k0 = blockIdx.x * 64;
    const int n0 = blockIdx.y * 64;

    const float* src = isH ? Wh : Wc;
    const int srcN   = isH ? 1024 : GATES;
    const int row0   = isH ? 0 : EMB;

    const int lr = tid >> 2;
    const int lc = (tid & 3) * 16;
    #pragma unroll
    for (int i = 0; i < 4; i++) {
        const float4 v = *(const float4*)(src + (size_t)(row0 + k0 + lr) * srcN + n0 + lc + i * 4);
        tile[lr][lc + i * 4 + 0] = v.x;
        tile[lr][lc + i * 4 + 1] = v.y;
        tile[lr][lc + i * 4 + 2] = v.z;
        tile[lr][lc + i * 4 + 3] = v.w;
    }
    __syncthreads();

    const int pl = tid >> 2;           // local col 0..63
    const int kq = (tid & 3) * 16;     // 16 k's per thread
    const int n = n0 + pl;
    int p;
    if (!isH) {
        const int qg = n >> 10, j = (n >> 5) & 31, l = n & 31;
        p = j * 128 + qg * 32 + l;
    } else {
        p = n;
    }
    __nv_bfloat16* dhi = (isH ? g_Hhi : g_Whi) + (size_t)p * WK + k0 + kq;
    __nv_bfloat16* dlo = (isH ? g_Hlo : g_Wlo) + (size_t)p * WK + k0 + kq;
    __nv_bfloat16 hb[16], lb[16];
    #pragma unroll
    for (int i = 0; i < 16; i++) {
        const float w = tile[kq + i][pl];
        const __nv_bfloat16 hi = __float2bfloat16(w);
        hb[i] = hi;
        lb[i] = __float2bfloat16(w - __bfloat162float(hi));
    }
    *(int4*)dhi = *(int4*)hb; *(int4*)(dhi + 8) = *(int4*)(hb + 8);
    *(int4*)dlo = *(int4*)lb; *(int4*)(dlo + 8) = *(int4*)(lb + 8);
}

// E'[v][p] = embed[v,:] @ W_cell[0:512, n(p)] + b[n] (+1 for f gate); double-buffered.
// Also initializes h0 (bf16 zeros) and the device barriers.
__global__ __launch_bounds__(256)
void prep_e(const float* __restrict__ A, const float* __restrict__ W,
            const float* __restrict__ bias)
{
    const int tid = threadIdx.x;
    {
        const int gid = (blockIdx.y * gridDim.x + blockIdx.x) * 256 + tid;  // 0..65535
        #pragma unroll
        for (int i = 0; i < 8; i++) {
            const int idx = gid + i * 65536;
            g_hbhi[0][idx] = __float2bfloat16(0.0f);
            g_hblo[0][idx] = __float2bfloat16(0.0f);
        }
        if (gid < 128) g_bar[gid] = 0u;
    }

    __shared__ float As[2][16][132];
    __shared__ float Bs[2][16][128];
    const int bm = blockIdx.y * 128;
    const int bn = blockIdx.x * 128;
    const int K = EMB, N = GATES;

    const int ar0 = tid >> 2, ar1 = ar0 + 64, akq = (tid & 3) * 4;
    const int br0 = tid >> 5, br1 = br0 + 8, bc = (tid & 31) * 4;
    const int tm = (tid >> 4) * 8, tn = (tid & 15) * 8;

    const float* aP0 = A + (size_t)(bm + ar0) * K + akq;
    const float* aP1 = A + (size_t)(bm + ar1) * K + akq;
    const float* bP0 = W + (size_t)br0 * N + bn + bc;
    const float* bP1 = W + (size_t)br1 * N + bn + bc;

    float acc[8][8];
    #pragma unroll
    for (int i = 0; i < 8; i++)
        #pragma unroll
        for (int j = 0; j < 8; j++) acc[i][j] = 0.0f;

    {
        const float4 va0 = *(const float4*)aP0;
        const float4 va1 = *(const float4*)aP1;
        const float4 vb0 = *(const float4*)bP0;
        const float4 vb1 = *(const float4*)bP1;
        As[0][akq + 0][ar0] = va0.x; As[0][akq + 1][ar0] = va0.y;
        As[0][akq + 2][ar0] = va0.z; As[0][akq + 3][ar0] = va0.w;
        As[0][akq + 0][ar1] = va1.x; As[0][akq + 1][ar1] = va1.y;
        As[0][akq + 2][ar1] = va1.z; As[0][akq + 3][ar1] = va1.w;
        *(float4*)&Bs[0][br0][bc] = vb0;
        *(float4*)&Bs[0][br1][bc] = vb1;
    }
    __syncthreads();

    int buf = 0;
    for (int k0 = 16; k0 <= K; k0 += 16) {
        const bool more = (k0 < K);
        float4 nva0, nva1, nvb0, nvb1;
        if (more) {
            nva0 = *(const float4*)(aP0 + k0);
            nva1 = *(const float4*)(aP1 + k0);
            nvb0 = *(const float4*)(bP0 + (size_t)k0 * N);
            nvb1 = *(const float4*)(bP1 + (size_t)k0 * N);
        }
        #pragma unroll
        for (int kk = 0; kk < 16; kk++) {
            float a[8], b[8];
            *(float4*)&a[0] = *(const float4*)&As[buf][kk][tm];
            *(float4*)&a[4] = *(const float4*)&As[buf][kk][tm + 4];
            *(float4*)&b[0] = *(const float4*)&Bs[buf][kk][tn];
            *(float4*)&b[4] = *(const float4*)&Bs[buf][kk][tn + 4];
            #pragma unroll
            for (int i = 0; i < 8; i++)
                #pragma unroll
                for (int j = 0; j < 8; j++)
                    acc[i][j] = fmaf(a[i], b[j], acc[i][j]);
        }
        if (more) {
            const int nb = buf ^ 1;
            As[nb][akq + 0][ar0] = nva0.x; As[nb][akq + 1][ar0] = nva0.y;
            As[nb][akq + 2][ar0] = nva0.z; As[nb][akq + 3][ar0] = nva0.w;
            As[nb][akq + 0][ar1] = nva1.x; As[nb][akq + 1][ar1] = nva1.y;
            As[nb][akq + 2][ar1] = nva1.z; As[nb][akq + 3][ar1] = nva1.w;
            *(float4*)&Bs[nb][br0][bc] = nvb0;
            *(float4*)&Bs[nb][br1][bc] = nvb1;
        }
        __syncthreads();
        buf ^= 1;
    }

    const int qg = bn >> 10;
    const float fadd = (qg == 2) ? 1.0f : 0.0f;
    float bia[8];
    *(float4*)&bia[0] = *(const float4*)(bias + bn + tn);
    *(float4*)&bia[4] = *(const float4*)(bias + bn + tn + 4);
    const int n0 = bn + tn;
    const int j0 = (n0 >> 5) & 31, l0 = n0 & 31;
    const int p0 = j0 * 128 + qg * 32 + l0;
    #pragma unroll
    for (int i = 0; i < 8; i++) {
        const int v = bm + tm + i;
        float4 o0, o1;
        o0.x = acc[i][0] + bia[0] + fadd; o0.y = acc[i][1] + bia[1] + fadd;
        o0.z = acc[i][2] + bia[2] + fadd; o0.w = acc[i][3] + bia[3] + fadd;
        o1.x = acc[i][4] + bia[4] + fadd; o1.y = acc[i][5] + bia[5] + fadd;
        o1.z = acc[i][6] + bia[6] + fadd; o1.w = acc[i][7] + bia[7] + fadd;
        float* dst = g_Ep + (size_t)v * GATES + p0;
        *(float4*)(dst)     = o0;
        *(float4*)(dst + 4) = o1;
    }
}

// ================= launch =================
extern "C" void kernel_launch(void* const* d_in, const int* in_sizes, int n_in,
                              void* d_out, int out_size)
{
    const float* images  = (const float*)d_in[0];
    const float* embed   = (const float*)d_in[1];
    const float* W_cell  = (const float*)d_in[2];
    const float* b_cell  = (const float*)d_in[3];
    const float* W_img   = (const float*)d_in[4];
    const float* b_img   = (const float*)d_in[5];
    const float* W_hid   = (const float*)d_in[6];
    const float* b_hid   = (const float*)d_in[7];
    const int*   message = (const int*)d_in[8];
    float* out = (float*)d_out;
    (void)in_sizes; (void)n_in; (void)out_size;

    static int smem_set = 0;
    if (!smem_set) {
        cudaFuncSetAttribute(lstm_persist, cudaFuncAttributeMaxDynamicSharedMemorySize, STEP_SMEM);
        smem_set = 1;
    }

    prep_w2<<<dim3(16, 64, 2), 256>>>(W_cell, W_hid);
    prep_e<<<dim3(GATES / 128, 1024 / 128), 256>>>(embed, W_cell, b_cell);

    // 128 LSTM CTAs + 16 images-projection CTAs, all co-resident (144 <= 148 SMs)
    lstm_persist<<<dim3(36, 4), NTHR, STEP_SMEM>>>(message, images, W_img, b_img, b_hid, out);
}

// round 15
// speedup vs baseline: 1.0052x; 1.0052x over previous
#include <cuda_runtime.h>
#include <cuda_bf16.h>
#include <math.h>
#include <stdint.h>

#define B_SZ   512
#define T_SZ   128
#define HID    1024
#define EMB    512
#define GATES  4096
#define WK     1024      // recurrent K (h only)
#define NCH    16        // chunks of 64 K-elems
#define NTHR   1024

// ---------------- device scratch (allocation-free) ----------------
__device__ __nv_bfloat16 g_Whi[GATES * WK];      // [p][k'] permuted N-major (h part)
__device__ __nv_bfloat16 g_Wlo[GATES * WK];
__device__ float g_Ep[1024 * GATES];             // E'[vocab][p]: emb@Wx + b (+1 on f)
__device__ __nv_bfloat16 g_hbhi[2][B_SZ * HID];  // double-buffered h (bf16 hi/lo)
__device__ __nv_bfloat16 g_hblo[2][B_SZ * HID];
__device__ float g_hf[B_SZ * HID];               // fp32 h (final projection)
__device__ unsigned g_bar[128];                  // 4 m-group barriers, stride 32

// ---------------- helpers ----------------
__device__ __forceinline__ uint32_t smem_u32(const void* p) {
    uint32_t r;
    asm("{ .reg .u64 t; cvta.to.shared.u64 t, %1; cvt.u32.u64 %0, t; }" : "=r"(r) : "l"(p));
    return r;
}
__device__ __forceinline__ void cpa16(uint32_t dst, const void* src) {
    asm volatile("cp.async.cg.shared.global [%0], [%1], 16;" :: "r"(dst), "l"(src) : "memory");
}
#define CP_COMMIT() asm volatile("cp.async.commit_group;" ::: "memory")
#define CP_WAIT1()  asm volatile("cp.async.wait_group 1;" ::: "memory")
#define CP_WAIT0()  asm volatile("cp.async.wait_group 0;" ::: "memory")

#define LDMX4(r, addr) \
    asm volatile("ldmatrix.sync.aligned.m8n8.x4.shared.b16 {%0,%1,%2,%3}, [%4];" \
        : "=r"((r)[0]), "=r"((r)[1]), "=r"((r)[2]), "=r"((r)[3]) : "r"(addr))

#define MMA(acc, a, b0, b1) \
    asm volatile("mma.sync.aligned.m16n8k16.row.col.f32.bf16.bf16.f32 " \
        "{%0,%1,%2,%3}, {%4,%5,%6,%7}, {%8,%9}, {%0,%1,%2,%3};" \
        : "+f"((acc)[0]), "+f"((acc)[1]), "+f"((acc)[2]), "+f"((acc)[3]) \
        : "r"((a)[0]), "r"((a)[1]), "r"((a)[2]), "r"((a)[3]), "r"(b0), "r"(b1))

#define SW(o) ((uint32_t)(o) ^ ((((uint32_t)(o)) >> 3) & 0x70))

__device__ __forceinline__ float sigm(float x) { return 1.0f / (1.0f + __expf(-x)); }
__device__ __forceinline__ float tanh_f(float x) {
    float e = __expf(2.0f * x);
    return 1.0f - 2.0f / (e + 1.0f);
}

// smem: 3 stages; each stage = 4 regions (Ahi/Alo/Bhi/Blo) of 128 rows x 128B.
// smC overlaps slot 1 — disjoint from slot0/slot2 B regions (pre-barrier prefetch).
#define OFF_AHI   0
#define OFF_ALO   16384
#define OFF_BHI   32768
#define OFF_BLO   49152
#define STAGE_SZ  65536
#define STEP_SMEM (3 * STAGE_SZ)   // 196608

#define PREF_A(base, kb) do { \
    cpa16((base) + OFF_AHI + sw0, aHhi + (kb) + go0); \
    cpa16((base) + OFF_ALO + sw0, aHlo + (kb) + go0); \
} while (0)
#define PREF_B(base, kb) do { \
    cpa16((base) + OFF_BHI + sw0, bWhi + (kb) + go0); \
    cpa16((base) + OFF_BLO + sw0, bWlo + (kb) + go0); \
} while (0)

// ---------------- in-kernel images projection (16 extra CTAs) ----------------
// C[pm:+128][pn:+256] = images[512,2048] @ W_img[2048,1024] + b ; double-buffered
__device__ void proj_images(char* smem, const float* __restrict__ A,
                            const float* __restrict__ W, const float* __restrict__ bias,
                            float* __restrict__ C, int pm, int pn, int tid)
{
    const int K = 2048, N = 1024;
    float (*As)[16][132] = (float(*)[16][132])smem;
    float (*Bs)[16][256] = (float(*)[16][256])(smem + 18432);

    const int ar = tid >> 3, ak = (tid & 7) * 2;
    const int br = tid >> 6, bc = (tid & 63) * 4;
    const int tm = (tid >> 5) * 4, tn = (tid & 31) * 8;

    const float* aP = A + (size_t)(pm + ar) * K + ak;
    const float* bP = W + (size_t)br * N + pn + bc;

    float acc[4][8];
    #pragma unroll
    for (int i = 0; i < 4; i++)
        #pragma unroll
        for (int j = 0; j < 8; j++) acc[i][j] = 0.0f;

    {
        const float2 va = *(const float2*)aP;
        const float4 vb = *(const float4*)bP;
        As[0][ak][ar] = va.x; As[0][ak + 1][ar] = va.y;
        *(float4*)&Bs[0][br][bc] = vb;
    }
    __syncthreads();

    int buf = 0;
    for (int k0 = 16; k0 <= K; k0 += 16) {
        const bool more = (k0 < K);
        float2 nva; float4 nvb;
        if (more) {
            nva = *(const float2*)(aP + k0);
            nvb = *(const float4*)(bP + (size_t)k0 * N);
        }
        #pragma unroll
        for (int kk = 0; kk < 16; kk++) {
            float a[4], b[8];
            *(float4*)&a[0] = *(const float4*)&As[buf][kk][tm];
            *(float4*)&b[0] = *(const float4*)&Bs[buf][kk][tn];
            *(float4*)&b[4] = *(const float4*)&Bs[buf][kk][tn + 4];
            #pragma unroll
            for (int i = 0; i < 4; i++)
                #pragma unroll
                for (int j = 0; j < 8; j++)
                    acc[i][j] = fmaf(a[i], b[j], acc[i][j]);
        }
        if (more) {
            const int nb = buf ^ 1;
            As[nb][ak][ar] = nva.x; As[nb][ak + 1][ar] = nva.y;
            *(float4*)&Bs[nb][br][bc] = nvb;
        }
        __syncthreads();
        buf ^= 1;
    }

    float bia[8];
    *(float4*)&bia[0] = *(const float4*)(bias + pn + tn);
    *(float4*)&bia[4] = *(const float4*)(bias + pn + tn + 4);
    #pragma unroll
    for (int i = 0; i < 4; i++) {
        float4 o0, o1;
        o0.x = acc[i][0] + bia[0]; o0.y = acc[i][1] + bia[1];
        o0.z = acc[i][2] + bia[2]; o0.w = acc[i][3] + bia[3];
        o1.x = acc[i][4] + bia[4]; o1.y = acc[i][5] + bia[5];
        o1.z = acc[i][6] + bia[6]; o1.w = acc[i][7] + bia[7];
        float* crow_ = C + (size_t)(pm + tm + i) * N + pn + tn;
        *(float4*)(crow_)     = o0;
        *(float4*)(crow_ + 4) = o1;
    }
}

// ========== persistent LSTM (all 128 steps) + overlapped images projection ==========
__global__ void __launch_bounds__(NTHR, 1)
lstm_persist(const int* __restrict__ message,
             const float* __restrict__ images, const float* __restrict__ W_img,
             const float* __restrict__ b_img, float* __restrict__ out)
{
    extern __shared__ __align__(1024) char smem[];
    const int tid = threadIdx.x;

    // ---- extra CTAs (bx >= 32): images projection on otherwise-idle SMs ----
    if (blockIdx.x >= 32) {
        const int id = (blockIdx.x - 32) * 4 + blockIdx.y;   // 0..15
        proj_images(smem, images, W_img, b_img, out,
                    (id >> 2) * 128, (id & 3) * 256, tid);
        return;
    }

    const uint32_t sm = smem_u32(smem);
    const int lane = tid & 31;
    const int wid  = tid >> 5;              // 0..31
    const int bx   = blockIdx.x;            // n-tile 0..31 (permuted cols)
    const int bm   = blockIdx.y * 128;      // m-tile base row

    // ---- loader addressing: 1024 threads, 1 row + 1 quarter each ----
    const int r = tid >> 3;                 // 0..127 tile row
    const int q = tid & 7;                  // 16B quarter of 128B row
    const char* bWhi = (const char*)(g_Whi + (size_t)(bx * 128 + r) * WK);
    const char* bWlo = (const char*)(g_Wlo + (size_t)(bx * 128 + r) * WK);
    const char* hHi[2] = { (const char*)(g_hbhi[0] + (size_t)(bm + r) * HID),
                           (const char*)(g_hbhi[1] + (size_t)(bm + r) * HID) };
    const char* hLo[2] = { (const char*)(g_hblo[0] + (size_t)(bm + r) * HID),
                           (const char*)(g_hblo[1] + (size_t)(bm + r) * HID) };
    const uint32_t sw0 = SW(r * 128 + q * 16);
    const int go0 = q * 16;

    // ---- warp compute layout: 4(M) x 8(N) warps; warp tile 32x16 ----
    const int wm = (wid >> 3) * 32;
    const int wn = (wid & 7) * 16;
    const int aRow = (lane & 15);
    const int aSel = ((lane >> 4) & 1) * 16;
    const int bRowBase = (lane & 7) + ((lane >> 4) & 1) * 8;
    const int bSel = ((lane >> 3) & 1) * 16;

    // ---- epilogue addressing: 8 threads per row, 4 cols each ----
    const int erow  = bm + (tid >> 3);
    const int esub  = tid & 7;
    const int* msgp = message + erow * T_SZ;
    float* hrow = g_hf + (size_t)erow * HID + bx * 32 + esub * 4;
    float* smC = (float*)(smem + STAGE_SZ);   // overlaps slot 1 (safe by schedule)

    // cell state lives in registers for ALL 128 steps (c0 = 0)
    float4 creg = make_float4(0.0f, 0.0f, 0.0f, 0.0f);

    // ---- initial pre-barrier weight prefetch (chunks 0 and 2; W only) ----
    PREF_B(sm, 0);
    PREF_B(sm + 2 * STAGE_SZ, 2 * 128);

    #pragma unroll 1
    for (int t = 0; t < T_SZ; t++) {
        const int msg = msgp[t];            // independent of h; loads early
        const char* aHhi = hHi[t & 1];
        const char* aHlo = hLo[t & 1];

        float acc[2][2][4];
        #pragma unroll
        for (int i = 0; i < 2; i++)
            #pragma unroll
            for (int j = 0; j < 2; j++)
                #pragma unroll
                for (int k = 0; k < 4; k++) acc[i][j][k] = 0.0f;

        // ---- post-barrier: A chunk 0 (group carries B0,B2), then chunk 1 A+B ----
        PREF_A(sm, 0);
        CP_COMMIT();
        PREF_A(sm + STAGE_SZ, 128);
        PREF_B(sm + STAGE_SZ, 128);
        CP_COMMIT();

        int sc = 0, sp = 2;
        #pragma unroll 1
        for (int c = 0; c < NCH; c++) {
            if (c < NCH - 1) { CP_WAIT1(); } else { CP_WAIT0(); }
            __syncthreads();   // chunk c visible to all; all warps done with slot sp

            if (c + 2 < NCH) {
                const uint32_t dst = sm + sp * STAGE_SZ;
                const int kb = (c + 2) * 128;
                PREF_A(dst, kb);
                if (c != 0) PREF_B(dst, kb);   // c==0: chunk2's B preloaded pre-barrier
                CP_COMMIT();
            }

            const uint32_t stage = sm + sc * STAGE_SZ;
            #pragma unroll
            for (int k16 = 0; k16 < 4; k16++) {
                const int kb = k16 * 32;
                uint32_t ah[2][4], al[2][4], bh[4], bl[4];
                #pragma unroll
                for (int mi = 0; mi < 2; mi++) {
                    const uint32_t ao = SW((wm + mi * 16 + aRow) * 128 + kb + aSel);
                    LDMX4(ah[mi], stage + OFF_AHI + ao);
                    LDMX4(al[mi], stage + OFF_ALO + ao);
                }
                {
                    const uint32_t bo = SW((wn + bRowBase) * 128 + kb + bSel);
                    LDMX4(bh, stage + OFF_BHI + bo);
                    LDMX4(bl, stage + OFF_BLO + bo);
                }
                #pragma unroll
                for (int mi = 0; mi < 2; mi++) {
                    #pragma unroll
                    for (int n8 = 0; n8 < 2; n8++) {
                        const uint32_t bh0 = bh[n8 * 2], bh1 = bh[n8 * 2 + 1];
                        const uint32_t bl0 = bl[n8 * 2], bl1 = bl[n8 * 2 + 1];
                        MMA(acc[mi][n8], ah[mi], bh0, bh1);
                        MMA(acc[mi][n8], al[mi], bh0, bh1);
                        MMA(acc[mi][n8], ah[mi], bl0, bl1);
                    }
                }
            }
            sc = (sc == 2) ? 0 : sc + 1;
            sp = (sp == 2) ? 0 : sp + 1;
        }

        __syncthreads();   // all warps done with all stage slots

        // ---- pre-barrier weight prefetch for NEXT step ----
        if (t + 1 < T_SZ) {
            PREF_B(sm, 0);
            PREF_B(sm + 2 * STAGE_SZ, 2 * 128);
        }

        // ---- stage accumulators to smC (fp32, stride 132) ----
        #pragma unroll
        for (int mi = 0; mi < 2; mi++) {
            #pragma unroll
            for (int n8 = 0; n8 < 2; n8++) {
                const int row = wm + mi * 16 + (lane >> 2);
                const int col = wn + n8 * 8 + (lane & 3) * 2;
                smC[row * 132 + col]           = acc[mi][n8][0];
                smC[row * 132 + col + 1]       = acc[mi][n8][1];
                smC[(row + 8) * 132 + col]     = acc[mi][n8][2];
                smC[(row + 8) * 132 + col + 1] = acc[mi][n8][3];
            }
        }
        __syncthreads();

        // ---- fused epilogue: 8 threads per row, 4 elems each; c in registers ----
        {
            const float* cr = smC + (tid >> 3) * 132 + esub * 4;
            const float* ep = g_Ep + (size_t)msg * GATES + bx * 128 + esub * 4;
            __nv_bfloat16* hh = g_hbhi[(t + 1) & 1] + (size_t)erow * HID + bx * 32 + esub * 4;
            __nv_bfloat16* hl = g_hblo[(t + 1) & 1] + (size_t)erow * HID + bx * 32 + esub * 4;
            float* cv = (float*)&creg;
            __nv_bfloat16 hhb[4], hlb[4];
            float hvb[4];
            #pragma unroll
            for (int l = 0; l < 4; l++) {
                const float iv = cr[l]      + ep[l];
                const float gv = cr[32 + l] + ep[32 + l];
                const float fv = cr[64 + l] + ep[64 + l];   // +1 folded
                const float ov = cr[96 + l] + ep[96 + l];
                const float cc = sigm(fv) * cv[l] + sigm(iv) * tanh_f(gv);
                const float hv = sigm(ov) * tanh_f(cc);
                cv[l] = cc;
                hvb[l] = hv;
                const __nv_bfloat16 hi = __float2bfloat16(hv);
                hhb[l] = hi;
                hlb[l] = __float2bfloat16(hv - __bfloat162float(hi));
            }
            *(int2*)hh = *(int2*)hhb;
            *(int2*)hl = *(int2*)hlb;
            if (t == T_SZ - 1) {
                *(float4*)hrow = *(float4*)hvb;
            }
        }

        // ---- per-m-group barrier (32 CTAs sharing this bm) ----
        if (t + 1 < T_SZ) {
            __threadfence();
            __syncthreads();
            if (tid == 0) {
                unsigned* bar = g_bar + (blockIdx.y << 5);
                atomicAdd(bar, 1u);
                const unsigned target = 32u * (unsigned)(t + 1);
                while (*(volatile unsigned*)bar < target) { __nanosleep(64); }
            }
            __syncthreads();
        }
    }
}

// ====== prep: coalesced tiled transpose + bf16 split for W_cell (h rows) ======
// grid (16, 64): 64x64 tiles of W_cell rows [512,1536) x cols [0,4096)
__global__ __launch_bounds__(256)
void prep_w2(const float* __restrict__ Wc)
{
    __shared__ float tile[64][65];
    const int tid = threadIdx.x;
    const int k0 = blockIdx.x * 64;
    const int n0 = blockIdx.y * 64;

    const int lr = tid >> 2;
    const int lc = (tid & 3) * 16;
    #pragma unroll
    for (int i = 0; i < 4; i++) {
        const float4 v = *(const float4*)(Wc + (size_t)(EMB + k0 + lr) * GATES + n0 + lc + i * 4);
        tile[lr][lc + i * 4 + 0] = v.x;
        tile[lr][lc + i * 4 + 1] = v.y;
        tile[lr][lc + i * 4 + 2] = v.z;
        tile[lr][lc + i * 4 + 3] = v.w;
    }
    __syncthreads();

    const int pl = tid >> 2;           // local col 0..63
    const int kq = (tid & 3) * 16;     // 16 k's per thread
    const int n = n0 + pl;
    const int qg = n >> 10, j = (n >> 5) & 31, l = n & 31;
    const int p = j * 128 + qg * 32 + l;
    __nv_bfloat16* dhi = g_Whi + (size_t)p * WK + k0 + kq;
    __nv_bfloat16* dlo = g_Wlo + (size_t)p * WK + k0 + kq;
    __nv_bfloat16 hb[16], lb[16];
    #pragma unroll
    for (int i = 0; i < 16; i++) {
        const float w = tile[kq + i][pl];
        const __nv_bfloat16 hi = __float2bfloat16(w);
        hb[i] = hi;
        lb[i] = __float2bfloat16(w - __bfloat162float(hi));
    }
    *(int4*)dhi = *(int4*)hb; *(int4*)(dhi + 8) = *(int4*)(hb + 8);
    *(int4*)dlo = *(int4*)lb; *(int4*)(dlo + 8) = *(int4*)(lb + 8);
}

// E'[v][p] = embed[v,:] @ W_cell[0:512, n(p)] + b[n] (+1 for f gate); double-buffered.
// Also initializes h0 (bf16 zeros) and the device barriers.
__global__ __launch_bounds__(256)
void prep_e(const float* __restrict__ A, const float* __restrict__ W,
            const float* __restrict__ bias)
{
    const int tid = threadIdx.x;
    {
        const int gid = (blockIdx.y * gridDim.x + blockIdx.x) * 256 + tid;  // 0..65535
        #pragma unroll
        for (int i = 0; i < 8; i++) {
            const int idx = gid + i * 65536;
            g_hbhi[0][idx] = __float2bfloat16(0.0f);
            g_hblo[0][idx] = __float2bfloat16(0.0f);
        }
        if (gid < 128) g_bar[gid] = 0u;
    }

    __shared__ float As[2][16][132];
    __shared__ float Bs[2][16][128];
    const int bm = blockIdx.y * 128;
    const int bn = blockIdx.x * 128;
    const int K = EMB, N = GATES;

    const int ar0 = tid >> 2, ar1 = ar0 + 64, akq = (tid & 3) * 4;
    const int br0 = tid >> 5, br1 = br0 + 8, bc = (tid & 31) * 4;
    const int tm = (tid >> 4) * 8, tn = (tid & 15) * 8;

    const float* aP0 = A + (size_t)(bm + ar0) * K + akq;
    const float* aP1 = A + (size_t)(bm + ar1) * K + akq;
    const float* bP0 = W + (size_t)br0 * N + bn + bc;
    const float* bP1 = W + (size_t)br1 * N + bn + bc;

    float acc[8][8];
    #pragma unroll
    for (int i = 0; i < 8; i++)
        #pragma unroll
        for (int j = 0; j < 8; j++) acc[i][j] = 0.0f;

    {
        const float4 va0 = *(const float4*)aP0;
        const float4 va1 = *(const float4*)aP1;
        const float4 vb0 = *(const float4*)bP0;
        const float4 vb1 = *(const float4*)bP1;
        As[0][akq + 0][ar0] = va0.x; As[0][akq + 1][ar0] = va0.y;
        As[0][akq + 2][ar0] = va0.z; As[0][akq + 3][ar0] = va0.w;
        As[0][akq + 0][ar1] = va1.x; As[0][akq + 1][ar1] = va1.y;
        As[0][akq + 2][ar1] = va1.z; As[0][akq + 3][ar1] = va1.w;
        *(float4*)&Bs[0][br0][bc] = vb0;
        *(float4*)&Bs[0][br1][bc] = vb1;
    }
    __syncthreads();

    int buf = 0;
    for (int k0 = 16; k0 <= K; k0 += 16) {
        const bool more = (k0 < K);
        float4 nva0, nva1, nvb0, nvb1;
        if (more) {
            nva0 = *(const float4*)(aP0 + k0);
            nva1 = *(const float4*)(aP1 + k0);
            nvb0 = *(const float4*)(bP0 + (size_t)k0 * N);
            nvb1 = *(const float4*)(bP1 + (size_t)k0 * N);
        }
        #pragma unroll
        for (int kk = 0; kk < 16; kk++) {
            float a[8], b[8];
            *(float4*)&a[0] = *(const float4*)&As[buf][kk][tm];
            *(float4*)&a[4] = *(const float4*)&As[buf][kk][tm + 4];
            *(float4*)&b[0] = *(const float4*)&Bs[buf][kk][tn];
            *(float4*)&b[4] = *(const float4*)&Bs[buf][kk][tn + 4];
            #pragma unroll
            for (int i = 0; i < 8; i++)
                #pragma unroll
                for (int j = 0; j < 8; j++)
                    acc[i][j] = fmaf(a[i], b[j], acc[i][j]);
        }
        if (more) {
            const int nb = buf ^ 1;
            As[nb][akq + 0][ar0] = nva0.x; As[nb][akq + 1][ar0] = nva0.y;
            As[nb][akq + 2][ar0] = nva0.z; As[nb][akq + 3][ar0] = nva0.w;
            As[nb][akq + 0][ar1] = nva1.x; As[nb][akq + 1][ar1] = nva1.y;
            As[nb][akq + 2][ar1] = nva1.z; As[nb][akq + 3][ar1] = nva1.w;
            *(float4*)&Bs[nb][br0][bc] = nvb0;
            *(float4*)&Bs[nb][br1][bc] = nvb1;
        }
        __syncthreads();
        buf ^= 1;
    }

    const int qg = bn >> 10;
    const float fadd = (qg == 2) ? 1.0f : 0.0f;
    float bia[8];
    *(float4*)&bia[0] = *(const float4*)(bias + bn + tn);
    *(float4*)&bia[4] = *(const float4*)(bias + bn + tn + 4);
    const int n0 = bn + tn;
    const int j0 = (n0 >> 5) & 31, l0 = n0 & 31;
    const int p0 = j0 * 128 + qg * 32 + l0;
    #pragma unroll
    for (int i = 0; i < 8; i++) {
        const int v = bm + tm + i;
        float4 o0, o1;
        o0.x = acc[i][0] + bia[0] + fadd; o0.y = acc[i][1] + bia[1] + fadd;
        o0.z = acc[i][2] + bia[2] + fadd; o0.w = acc[i][3] + bia[3] + fadd;
        o1.x = acc[i][4] + bia[4] + fadd; o1.y = acc[i][5] + bia[5] + fadd;
        o1.z = acc[i][6] + bia[6] + fadd; o1.w = acc[i][7] + bia[7] + fadd;
        float* dst = g_Ep + (size_t)v * GATES + p0;
        *(float4*)(dst)     = o0;
        *(float4*)(dst + 4) = o1;
    }
}

// ====== 64x64-tile fp32 GEMM, double-buffered (hidden projection) ======
__global__ __launch_bounds__(256)
void gemm64h(const float* __restrict__ W, const float* __restrict__ bias,
             float* __restrict__ C, int N, int K)
{
    __shared__ float As[2][16][68];
    __shared__ float Bs[2][16][64];
    const int tid = threadIdx.x;
    const int bm = blockIdx.y * 64;
    const int bn = blockIdx.x * 64;
    const float* Ab = (const float*)g_hf;

    const int ar = tid >> 2, ak = (tid & 3) * 4;
    const int br = tid >> 4, bc = (tid & 15) * 4;
    const int tm = (tid >> 4) * 4, tn = (tid & 15) * 4;

    const float* aP = Ab + (size_t)(bm + ar) * K + ak;
    const float* bP = W + (size_t)br * N + bn + bc;

    float acc[4][4];
    #pragma unroll
    for (int i = 0; i < 4; i++)
        #pragma unroll
        for (int j = 0; j < 4; j++) acc[i][j] = 0.0f;

    {
        const float4 va = *(const float4*)(aP);
        const float4 vb = *(const float4*)(bP);
        As[0][ak + 0][ar] = va.x; As[0][ak + 1][ar] = va.y;
        As[0][ak + 2][ar] = va.z; As[0][ak + 3][ar] = va.w;
        *(float4*)&Bs[0][br][bc] = vb;
    }
    __syncthreads();

    int buf = 0;
    for (int k0 = 16; k0 <= K; k0 += 16) {
        float4 nva, nvb;
        const bool more = (k0 < K);
        if (more) {
            nva = *(const float4*)(aP + k0);
            nvb = *(const float4*)(bP + (size_t)k0 * N);
        }
        #pragma unroll
        for (int kk = 0; kk < 16; kk++) {
            float a[4], b[4];
            *(float4*)&a[0] = *(const float4*)&As[buf][kk][tm];
            *(float4*)&b[0] = *(const float4*)&Bs[buf][kk][tn];
            #pragma unroll
            for (int i = 0; i < 4; i++)
                #pragma unroll
                for (int j = 0; j < 4; j++)
                    acc[i][j] = fmaf(a[i], b[j], acc[i][j]);
        }
        if (more) {
            const int nb = buf ^ 1;
            As[nb][ak + 0][ar] = nva.x; As[nb][ak + 1][ar] = nva.y;
            As[nb][ak + 2][ar] = nva.z; As[nb][ak + 3][ar] = nva.w;
            *(float4*)&Bs[nb][br][bc] = nvb;
        }
        __syncthreads();
        buf ^= 1;
    }

    float4 bia = *(const float4*)(bias + bn + tn);
    #pragma unroll
    for (int i = 0; i < 4; i++) {
        float4 o;
        o.x = acc[i][0] + bia.x; o.y = acc[i][1] + bia.y;
        o.z = acc[i][2] + bia.z; o.w = acc[i][3] + bia.w;
        *(float4*)(C + (size_t)(bm + tm + i) * N + bn + tn) = o;
    }
}

// ================= launch =================
extern "C" void kernel_launch(void* const* d_in, const int* in_sizes, int n_in,
                              void* d_out, int out_size)
{
    const float* images  = (const float*)d_in[0];
    const float* embed   = (const float*)d_in[1];
    const float* W_cell  = (const float*)d_in[2];
    const float* b_cell  = (const float*)d_in[3];
    const float* W_img   = (const float*)d_in[4];
    const float* b_img   = (const float*)d_in[5];
    const float* W_hid   = (const float*)d_in[6];
    const float* b_hid   = (const float*)d_in[7];
    const int*   message = (const int*)d_in[8];
    float* out = (float*)d_out;
    (void)in_sizes; (void)n_in; (void)out_size;

    static int smem_set = 0;
    if (!smem_set) {
        cudaFuncSetAttribute(lstm_persist, cudaFuncAttributeMaxDynamicSharedMemorySize, STEP_SMEM);
        smem_set = 1;
    }

    prep_w2<<<dim3(16, 64), 256>>>(W_cell);
    prep_e<<<dim3(GATES / 128, 1024 / 128), 256>>>(embed, W_cell, b_cell);

    // 128 LSTM CTAs + 16 images-projection CTAs, all co-resident (144 <= 148 SMs)
    lstm_persist<<<dim3(36, 4), NTHR, STEP_SMEM>>>(message, images, W_img, b_img, out);

    gemm64h<<<dim3(1024 / 64, B_SZ / 64), 256>>>(W_hid, b_hid,
                                                 out + (size_t)B_SZ * HID, 1024, 1024);
}

// round 16
// speedup vs baseline: 1.0281x; 1.0228x over previous
#include <cuda_runtime.h>
#include <cuda_bf16.h>
#include <math.h>
#include <stdint.h>

#define B_SZ   512
#define T_SZ   128
#define HID    1024
#define EMB    512
#define GATES  4096
#define WK     1024      // recurrent K (h only)
#define NCH    16        // chunks of 64 K-elems
#define NTHR   1024

// ---------------- device scratch (allocation-free) ----------------
__device__ __nv_bfloat16 g_Whi[GATES * WK];      // [p][k'] permuted N-major (h part)
__device__ __nv_bfloat16 g_Wlo[GATES * WK];
__device__ __nv_bfloat16 g_Xhi[GATES * EMB];     // [p][k] permuted N-major (x part)
__device__ __nv_bfloat16 g_Xlo[GATES * EMB];
__device__ __nv_bfloat16 g_Hhi[HID * WK];        // W_hid split, N-major [n][k]
__device__ __nv_bfloat16 g_Hlo[HID * WK];
__device__ __nv_bfloat16 g_Ehi[1024 * EMB];      // embed split, [v][k]
__device__ __nv_bfloat16 g_Elo[1024 * EMB];
__device__ float g_bp[GATES];                    // permuted bias (+1 on f)
__device__ float g_Ep[1024 * GATES];             // E'[vocab][p]
__device__ __nv_bfloat16 g_hbhi[2][B_SZ * HID];  // double-buffered h (bf16 hi/lo)
__device__ __nv_bfloat16 g_hblo[2][B_SZ * HID];
__device__ unsigned g_bar[128];                  // 4 m-group barriers, stride 32

// ---------------- helpers ----------------
__device__ __forceinline__ uint32_t smem_u32(const void* p) {
    uint32_t r;
    asm("{ .reg .u64 t; cvta.to.shared.u64 t, %1; cvt.u32.u64 %0, t; }" : "=r"(r) : "l"(p));
    return r;
}
__device__ __forceinline__ void cpa16(uint32_t dst, const void* src) {
    asm volatile("cp.async.cg.shared.global [%0], [%1], 16;" :: "r"(dst), "l"(src) : "memory");
}
#define CP_COMMIT() asm volatile("cp.async.commit_group;" ::: "memory")
#define CP_WAIT1()  asm volatile("cp.async.wait_group 1;" ::: "memory")
#define CP_WAIT0()  asm volatile("cp.async.wait_group 0;" ::: "memory")

#define LDMX4(r, addr) \
    asm volatile("ldmatrix.sync.aligned.m8n8.x4.shared.b16 {%0,%1,%2,%3}, [%4];" \
        : "=r"((r)[0]), "=r"((r)[1]), "=r"((r)[2]), "=r"((r)[3]) : "r"(addr))

#define MMA(acc, a, b0, b1) \
    asm volatile("mma.sync.aligned.m16n8k16.row.col.f32.bf16.bf16.f32 " \
        "{%0,%1,%2,%3}, {%4,%5,%6,%7}, {%8,%9}, {%0,%1,%2,%3};" \
        : "+f"((acc)[0]), "+f"((acc)[1]), "+f"((acc)[2]), "+f"((acc)[3]) \
        : "r"((a)[0]), "r"((a)[1]), "r"((a)[2]), "r"((a)[3]), "r"(b0), "r"(b1))

#define SW(o) ((uint32_t)(o) ^ ((((uint32_t)(o)) >> 3) & 0x70))

__device__ __forceinline__ float sigm(float x) { return 1.0f / (1.0f + __expf(-x)); }
__device__ __forceinline__ float tanh_f(float x) {
    float e = __expf(2.0f * x);
    return 1.0f - 2.0f / (e + 1.0f);
}

// smem: 3 stages; each stage = 4 regions (Ahi/Alo/Bhi/Blo) of 128 rows x 128B.
#define OFF_AHI   0
#define OFF_ALO   16384
#define OFF_BHI   32768
#define OFF_BLO   49152
#define STAGE_SZ  65536
#define STEP_SMEM (3 * STAGE_SZ)   // 196608

#define PREF_A(base, kb) do { \
    cpa16((base) + OFF_AHI + sw0, aHhi + (kb) + go0); \
    cpa16((base) + OFF_ALO + sw0, aHlo + (kb) + go0); \
} while (0)
#define PREF_B(base, kb) do { \
    cpa16((base) + OFF_BHI + sw0, bWhi + (kb) + go0); \
    cpa16((base) + OFF_BLO + sw0, bWlo + (kb) + go0); \
} while (0)

// ---------------- in-kernel images projection (16 extra CTAs) ----------------
__device__ void proj_images(char* smem, const float* __restrict__ A,
                            const float* __restrict__ W, const float* __restrict__ bias,
                            float* __restrict__ C, int pm, int pn, int tid)
{
    const int K = 2048, N = 1024;
    float (*As)[16][132] = (float(*)[16][132])smem;
    float (*Bs)[16][256] = (float(*)[16][256])(smem + 18432);

    const int ar = tid >> 3, ak = (tid & 7) * 2;
    const int br = tid >> 6, bc = (tid & 63) * 4;
    const int tm = (tid >> 5) * 4, tn = (tid & 31) * 8;

    const float* aP = A + (size_t)(pm + ar) * K + ak;
    const float* bP = W + (size_t)br * N + pn + bc;

    float acc[4][8];
    #pragma unroll
    for (int i = 0; i < 4; i++)
        #pragma unroll
        for (int j = 0; j < 8; j++) acc[i][j] = 0.0f;

    {
        const float2 va = *(const float2*)aP;
        const float4 vb = *(const float4*)bP;
        As[0][ak][ar] = va.x; As[0][ak + 1][ar] = va.y;
        *(float4*)&Bs[0][br][bc] = vb;
    }
    __syncthreads();

    int buf = 0;
    for (int k0 = 16; k0 <= K; k0 += 16) {
        const bool more = (k0 < K);
        float2 nva; float4 nvb;
        if (more) {
            nva = *(const float2*)(aP + k0);
            nvb = *(const float4*)(bP + (size_t)k0 * N);
        }
        #pragma unroll
        for (int kk = 0; kk < 16; kk++) {
            float a[4], b[8];
            *(float4*)&a[0] = *(const float4*)&As[buf][kk][tm];
            *(float4*)&b[0] = *(const float4*)&Bs[buf][kk][tn];
            *(float4*)&b[4] = *(const float4*)&Bs[buf][kk][tn + 4];
            #pragma unroll
            for (int i = 0; i < 4; i++)
                #pragma unroll
                for (int j = 0; j < 8; j++)
                    acc[i][j] = fmaf(a[i], b[j], acc[i][j]);
        }
        if (more) {
            const int nb = buf ^ 1;
            As[nb][ak][ar] = nva.x; As[nb][ak + 1][ar] = nva.y;
            *(float4*)&Bs[nb][br][bc] = nvb;
        }
        __syncthreads();
        buf ^= 1;
    }

    float bia[8];
    *(float4*)&bia[0] = *(const float4*)(bias + pn + tn);
    *(float4*)&bia[4] = *(const float4*)(bias + pn + tn + 4);
    #pragma unroll
    for (int i = 0; i < 4; i++) {
        float4 o0, o1;
        o0.x = acc[i][0] + bia[0]; o0.y = acc[i][1] + bia[1];
        o0.z = acc[i][2] + bia[2]; o0.w = acc[i][3] + bia[3];
        o1.x = acc[i][4] + bia[4]; o1.y = acc[i][5] + bia[5];
        o1.z = acc[i][6] + bia[6]; o1.w = acc[i][7] + bia[7];
        float* crow_ = C + (size_t)(pm + tm + i) * N + pn + tn;
        *(float4*)(crow_)     = o0;
        *(float4*)(crow_ + 4) = o1;
    }
}

// ========== persistent LSTM (all 128 steps) + overlapped images projection ==========
__global__ void __launch_bounds__(NTHR, 1)
lstm_persist(const int* __restrict__ message,
             const float* __restrict__ images, const float* __restrict__ W_img,
             const float* __restrict__ b_img, float* __restrict__ out)
{
    extern __shared__ __align__(1024) char smem[];
    const int tid = threadIdx.x;

    if (blockIdx.x >= 32) {
        const int id = (blockIdx.x - 32) * 4 + blockIdx.y;
        proj_images(smem, images, W_img, b_img, out,
                    (id >> 2) * 128, (id & 3) * 256, tid);
        return;
    }

    const uint32_t sm = smem_u32(smem);
    const int lane = tid & 31;
    const int wid  = tid >> 5;
    const int bx   = blockIdx.x;
    const int bm   = blockIdx.y * 128;

    const int r = tid >> 3;
    const int q = tid & 7;
    const char* bWhi = (const char*)(g_Whi + (size_t)(bx * 128 + r) * WK);
    const char* bWlo = (const char*)(g_Wlo + (size_t)(bx * 128 + r) * WK);
    const char* hHi[2] = { (const char*)(g_hbhi[0] + (size_t)(bm + r) * HID),
                           (const char*)(g_hbhi[1] + (size_t)(bm + r) * HID) };
    const char* hLo[2] = { (const char*)(g_hblo[0] + (size_t)(bm + r) * HID),
                           (const char*)(g_hblo[1] + (size_t)(bm + r) * HID) };
    const uint32_t sw0 = SW(r * 128 + q * 16);
    const int go0 = q * 16;

    const int wm = (wid >> 3) * 32;
    const int wn = (wid & 7) * 16;
    const int aRow = (lane & 15);
    const int aSel = ((lane >> 4) & 1) * 16;
    const int bRowBase = (lane & 7) + ((lane >> 4) & 1) * 8;
    const int bSel = ((lane >> 3) & 1) * 16;

    const int erow  = bm + (tid >> 3);
    const int esub  = tid & 7;
    const int* msgp = message + erow * T_SZ;
    float* smC = (float*)(smem + STAGE_SZ);

    float4 creg = make_float4(0.0f, 0.0f, 0.0f, 0.0f);

    PREF_B(sm, 0);
    PREF_B(sm + 2 * STAGE_SZ, 2 * 128);

    #pragma unroll 1
    for (int t = 0; t < T_SZ; t++) {
        const int msg = msgp[t];
        const char* aHhi = hHi[t & 1];
        const char* aHlo = hLo[t & 1];

        float acc[2][2][4];
        #pragma unroll
        for (int i = 0; i < 2; i++)
            #pragma unroll
            for (int j = 0; j < 2; j++)
                #pragma unroll
                for (int k = 0; k < 4; k++) acc[i][j][k] = 0.0f;

        PREF_A(sm, 0);
        CP_COMMIT();
        PREF_A(sm + STAGE_SZ, 128);
        PREF_B(sm + STAGE_SZ, 128);
        CP_COMMIT();

        int sc = 0, sp = 2;
        #pragma unroll 1
        for (int c = 0; c < NCH; c++) {
            if (c < NCH - 1) { CP_WAIT1(); } else { CP_WAIT0(); }
            __syncthreads();

            if (c + 2 < NCH) {
                const uint32_t dst = sm + sp * STAGE_SZ;
                const int kb = (c + 2) * 128;
                PREF_A(dst, kb);
                if (c != 0) PREF_B(dst, kb);
                CP_COMMIT();
            }

            const uint32_t stage = sm + sc * STAGE_SZ;
            #pragma unroll
            for (int k16 = 0; k16 < 4; k16++) {
                const int kb = k16 * 32;
                uint32_t ah[2][4], al[2][4], bh[4], bl[4];
                #pragma unroll
                for (int mi = 0; mi < 2; mi++) {
                    const uint32_t ao = SW((wm + mi * 16 + aRow) * 128 + kb + aSel);
                    LDMX4(ah[mi], stage + OFF_AHI + ao);
                    LDMX4(al[mi], stage + OFF_ALO + ao);
                }
                {
                    const uint32_t bo = SW((wn + bRowBase) * 128 + kb + bSel);
                    LDMX4(bh, stage + OFF_BHI + bo);
                    LDMX4(bl, stage + OFF_BLO + bo);
                }
                #pragma unroll
                for (int mi = 0; mi < 2; mi++) {
                    #pragma unroll
                    for (int n8 = 0; n8 < 2; n8++) {
                        const uint32_t bh0 = bh[n8 * 2], bh1 = bh[n8 * 2 + 1];
                        const uint32_t bl0 = bl[n8 * 2], bl1 = bl[n8 * 2 + 1];
                        MMA(acc[mi][n8], ah[mi], bh0, bh1);
                        MMA(acc[mi][n8], al[mi], bh0, bh1);
                        MMA(acc[mi][n8], ah[mi], bl0, bl1);
                    }
                }
            }
            sc = (sc == 2) ? 0 : sc + 1;
            sp = (sp == 2) ? 0 : sp + 1;
        }

        __syncthreads();

        if (t + 1 < T_SZ) {
            PREF_B(sm, 0);
            PREF_B(sm + 2 * STAGE_SZ, 2 * 128);
        }

        #pragma unroll
        for (int mi = 0; mi < 2; mi++) {
            #pragma unroll
            for (int n8 = 0; n8 < 2; n8++) {
                const int row = wm + mi * 16 + (lane >> 2);
                const int col = wn + n8 * 8 + (lane & 3) * 2;
                smC[row * 132 + col]           = acc[mi][n8][0];
                smC[row * 132 + col + 1]       = acc[mi][n8][1];
                smC[(row + 8) * 132 + col]     = acc[mi][n8][2];
                smC[(row + 8) * 132 + col + 1] = acc[mi][n8][3];
            }
        }
        __syncthreads();

        {
            const float* cr = smC + (tid >> 3) * 132 + esub * 4;
            const float* ep = g_Ep + (size_t)msg * GATES + bx * 128 + esub * 4;
            __nv_bfloat16* hh = g_hbhi[(t + 1) & 1] + (size_t)erow * HID + bx * 32 + esub * 4;
            __nv_bfloat16* hl = g_hblo[(t + 1) & 1] + (size_t)erow * HID + bx * 32 + esub * 4;
            float* cv = (float*)&creg;
            __nv_bfloat16 hhb[4], hlb[4];
            #pragma unroll
            for (int l = 0; l < 4; l++) {
                const float iv = cr[l]      + ep[l];
                const float gv = cr[32 + l] + ep[32 + l];
                const float fv = cr[64 + l] + ep[64 + l];
                const float ov = cr[96 + l] + ep[96 + l];
                const float cc = sigm(fv) * cv[l] + sigm(iv) * tanh_f(gv);
                const float hv = sigm(ov) * tanh_f(cc);
                cv[l] = cc;
                const __nv_bfloat16 hi = __float2bfloat16(hv);
                hhb[l] = hi;
                hlb[l] = __float2bfloat16(hv - __bfloat162float(hi));
            }
            *(int2*)hh = *(int2*)hhb;
            *(int2*)hl = *(int2*)hlb;
        }

        if (t + 1 < T_SZ) {
            __threadfence();
            __syncthreads();
            if (tid == 0) {
                unsigned* bar = g_bar + (blockIdx.y << 5);
                atomicAdd(bar, 1u);
                const unsigned target = 32u * (unsigned)(t + 1);
                while (*(volatile unsigned*)bar < target) { __nanosleep(64); }
            }
            __syncthreads();
        }
    }
}

// ====== generic bf16 3-pass MMA GEMM: 128x128 tile per CTA, same machinery ======
// mode 0: E' = embedsplit @ Xsplit(permuted) + g_bp  -> g_Ep (ldc=4096), K=512
// mode 1: proj = h_final @ Hsplit + bias_ext -> c_ext (ldc=1024), K=1024
__global__ void __launch_bounds__(NTHR, 1)
mma_gemm(int mode, const float* __restrict__ bias_ext, float* __restrict__ c_ext)
{
    extern __shared__ __align__(1024) char smem[];
    const uint32_t sm = smem_u32(smem);
    const int tid  = threadIdx.x;
    const int lane = tid & 31;
    const int wid  = tid >> 5;
    const int bx   = blockIdx.x;
    const int bm   = blockIdx.y * 128;

    const int nch = mode ? 16 : 8;
    const int Kb  = mode ? (WK * 2) : (EMB * 2);     // row stride in bytes
    const float* bias = mode ? bias_ext : g_bp;
    float* C  = mode ? c_ext : g_Ep;
    const int ldc = mode ? 1024 : GATES;

    const int r = tid >> 3;
    const int q = tid & 7;
    const char* aHhi, *aHlo, *bWhi, *bWlo;
    if (mode) {
        aHhi = (const char*)g_hbhi[0] + (size_t)(bm + r) * Kb;
        aHlo = (const char*)g_hblo[0] + (size_t)(bm + r) * Kb;
        bWhi = (const char*)g_Hhi + (size_t)(bx * 128 + r) * Kb;
        bWlo = (const char*)g_Hlo + (size_t)(bx * 128 + r) * Kb;
    } else {
        aHhi = (const char*)g_Ehi + (size_t)(bm + r) * Kb;
        aHlo = (const char*)g_Elo + (size_t)(bm + r) * Kb;
        bWhi = (const char*)g_Xhi + (size_t)(bx * 128 + r) * Kb;
        bWlo = (const char*)g_Xlo + (size_t)(bx * 128 + r) * Kb;
    }
    const uint32_t sw0 = SW(r * 128 + q * 16);
    const int go0 = q * 16;

    const int wm = (wid >> 3) * 32;
    const int wn = (wid & 7) * 16;
    const int aRow = (lane & 15);
    const int aSel = ((lane >> 4) & 1) * 16;
    const int bRowBase = (lane & 7) + ((lane >> 4) & 1) * 8;
    const int bSel = ((lane >> 3) & 1) * 16;
    float* smC = (float*)(smem + STAGE_SZ);

    float acc[2][2][4];
    #pragma unroll
    for (int i = 0; i < 2; i++)
        #pragma unroll
        for (int j = 0; j < 2; j++)
            #pragma unroll
            for (int k = 0; k < 4; k++) acc[i][j][k] = 0.0f;

    PREF_A(sm, 0); PREF_B(sm, 0);
    CP_COMMIT();
    PREF_A(sm + STAGE_SZ, 128); PREF_B(sm + STAGE_SZ, 128);
    CP_COMMIT();

    int sc = 0, sp = 2;
    #pragma unroll 1
    for (int c = 0; c < nch; c++) {
        if (c < nch - 1) { CP_WAIT1(); } else { CP_WAIT0(); }
        __syncthreads();

        if (c + 2 < nch) {
            const uint32_t dst = sm + sp * STAGE_SZ;
            const int kb = (c + 2) * 128;
            PREF_A(dst, kb); PREF_B(dst, kb);
            CP_COMMIT();
        }

        const uint32_t stage = sm + sc * STAGE_SZ;
        #pragma unroll
        for (int k16 = 0; k16 < 4; k16++) {
            const int kb = k16 * 32;
            uint32_t ah[2][4], al[2][4], bh[4], bl[4];
            #pragma unroll
            for (int mi = 0; mi < 2; mi++) {
                const uint32_t ao = SW((wm + mi * 16 + aRow) * 128 + kb + aSel);
                LDMX4(ah[mi], stage + OFF_AHI + ao);
                LDMX4(al[mi], stage + OFF_ALO + ao);
            }
            {
                const uint32_t bo = SW((wn + bRowBase) * 128 + kb + bSel);
                LDMX4(bh, stage + OFF_BHI + bo);
                LDMX4(bl, stage + OFF_BLO + bo);
            }
            #pragma unroll
            for (int mi = 0; mi < 2; mi++) {
                #pragma unroll
                for (int n8 = 0; n8 < 2; n8++) {
                    const uint32_t bh0 = bh[n8 * 2], bh1 = bh[n8 * 2 + 1];
                    const uint32_t bl0 = bl[n8 * 2], bl1 = bl[n8 * 2 + 1];
                    MMA(acc[mi][n8], ah[mi], bh0, bh1);
                    MMA(acc[mi][n8], al[mi], bh0, bh1);
                    MMA(acc[mi][n8], ah[mi], bl0, bl1);
                }
            }
        }
        sc = (sc == 2) ? 0 : sc + 1;
        sp = (sp == 2) ? 0 : sp + 1;
    }

    __syncthreads();
    #pragma unroll
    for (int mi = 0; mi < 2; mi++) {
        #pragma unroll
        for (int n8 = 0; n8 < 2; n8++) {
            const int row = wm + mi * 16 + (lane >> 2);
            const int col = wn + n8 * 8 + (lane & 3) * 2;
            smC[row * 132 + col]           = acc[mi][n8][0];
            smC[row * 132 + col + 1]       = acc[mi][n8][1];
            smC[(row + 8) * 132 + col]     = acc[mi][n8][2];
            smC[(row + 8) * 132 + col + 1] = acc[mi][n8][3];
        }
    }
    __syncthreads();

    {
        const int row = tid >> 3;
        const int e = tid & 7;
        const float* cr = smC + row * 132 + e * 16;
        const int gcol = bx * 128 + e * 16;
        float* op = C + (size_t)(bm + row) * ldc + gcol;
        #pragma unroll
        for (int j = 0; j < 4; j++) {
            float4 v = *(const float4*)(cr + j * 4);
            const float4 b = *(const float4*)(bias + gcol + j * 4);
            v.x += b.x; v.y += b.y; v.z += b.z; v.w += b.w;
            *(float4*)(op + j * 4) = v;
        }
    }
}

// ====== prep: all splits/transposes + bias + init, one launch ======
// grid (16, 64, 4):
//  z=0: W_cell rows [512,1536) -> g_Whi/g_Wlo (gate-permuted, transposed)
//  z=1: W_cell rows [0,512)    -> g_Xhi/g_Xlo (gate-permuted, transposed)   [x<8]
//  z=2: embed split + h0 init + permuted bias + barrier reset
//  z=3: W_hid -> g_Hhi/g_Hlo (transposed, no permute)                        [x<16, y<16]
__global__ __launch_bounds__(256)
void prep_w2(const float* __restrict__ Wc, const float* __restrict__ Wh,
             const float* __restrict__ Emb, const float* __restrict__ b_cell)
{
    const int tid = threadIdx.x;
    const int z = blockIdx.z;

    if (z == 2) {
        const int blk = blockIdx.y * 16 + blockIdx.x;        // 0..1023
        const int base = blk * 512 + tid * 2;                // covers 1024*512 elems
        {
            const float2 v = *(const float2*)(Emb + base);
            const __nv_bfloat16 h0 = __float2bfloat16(v.x);
            const __nv_bfloat16 h1 = __float2bfloat16(v.y);
            g_Ehi[base]     = h0;
            g_Ehi[base + 1] = h1;
            g_Elo[base]     = __float2bfloat16(v.x - __bfloat162float(h0));
            g_Elo[base + 1] = __float2bfloat16(v.y - __bfloat162float(h1));
            // h0 init (same index space: B_SZ*HID = 524288)
            const __nv_bfloat16 zb = __float2bfloat16(0.0f);
            g_hbhi[0][base] = zb; g_hbhi[0][base + 1] = zb;
            g_hblo[0][base] = zb; g_hblo[0][base + 1] = zb;
        }
        if (blk < 16) {
            const int p = blk * 256 + tid;                   // 0..4095
            const int j = p >> 7, qg = (p >> 5) & 3, l = p & 31;
            const int n = qg * 1024 + j * 32 + l;
            g_bp[p] = b_cell[n] + (qg == 2 ? 1.0f : 0.0f);
        }
        if (blk == 0 && tid < 128) g_bar[tid] = 0u;
        return;
    }

    __shared__ float tile[64][65];
    if (z == 1 && blockIdx.x >= 8) return;
    if (z == 3 && (blockIdx.x >= 16 || blockIdx.y >= 16)) return;

    const int k0 = blockIdx.x * 64;
    const int n0 = blockIdx.y * 64;
    const float* src = (z == 3) ? Wh : Wc;
    const int srcN   = (z == 3) ? 1024 : GATES;
    const int row0   = (z == 0) ? EMB : 0;

    const int lr = tid >> 2;
    const int lc = (tid & 3) * 16;
    #pragma unroll
    for (int i = 0; i < 4; i++) {
        const float4 v = *(const float4*)(src + (size_t)(row0 + k0 + lr) * srcN + n0 + lc + i * 4);
        tile[lr][lc + i * 4 + 0] = v.x;
        tile[lr][lc + i * 4 + 1] = v.y;
        tile[lr][lc + i * 4 + 2] = v.z;
        tile[lr][lc + i * 4 + 3] = v.w;
    }
    __syncthreads();

    const int pl = tid >> 2;
    const int kq = (tid & 3) * 16;
    const int n = n0 + pl;
    int p;
    if (z == 3) {
        p = n;
    } else {
        const int qg = n >> 10, j = (n >> 5) & 31, l = n & 31;
        p = j * 128 + qg * 32 + l;
    }
    const int kstride = (z == 1) ? EMB : WK;
    __nv_bfloat16* dhi = (z == 0 ? g_Whi : (z == 1 ? g_Xhi : g_Hhi)) + (size_t)p * kstride + k0 + kq;
    __nv_bfloat16* dlo = (z == 0 ? g_Wlo : (z == 1 ? g_Xlo : g_Hlo)) + (size_t)p * kstride + k0 + kq;
    __nv_bfloat16 hb[16], lb[16];
    #pragma unroll
    for (int i = 0; i < 16; i++) {
        const float w = tile[kq + i][pl];
        const __nv_bfloat16 hi = __float2bfloat16(w);
        hb[i] = hi;
        lb[i] = __float2bfloat16(w - __bfloat162float(hi));
    }
    *(int4*)dhi = *(int4*)hb; *(int4*)(dhi + 8) = *(int4*)(hb + 8);
    *(int4*)dlo = *(int4*)lb; *(int4*)(dlo + 8) = *(int4*)(lb + 8);
}

// ================= launch =================
extern "C" void kernel_launch(void* const* d_in, const int* in_sizes, int n_in,
                              void* d_out, int out_size)
{
    const float* images  = (const float*)d_in[0];
    const float* embed   = (const float*)d_in[1];
    const float* W_cell  = (const float*)d_in[2];
    const float* b_cell  = (const float*)d_in[3];
    const float* W_img   = (const float*)d_in[4];
    const float* b_img   = (const float*)d_in[5];
    const float* W_hid   = (const float*)d_in[6];
    const float* b_hid   = (const float*)d_in[7];
    const int*   message = (const int*)d_in[8];
    float* out = (float*)d_out;
    (void)in_sizes; (void)n_in; (void)out_size;

    static int smem_set = 0;
    if (!smem_set) {
        cudaFuncSetAttribute(lstm_persist, cudaFuncAttributeMaxDynamicSharedMemorySize, STEP_SMEM);
        cudaFuncSetAttribute(mma_gemm, cudaFuncAttributeMaxDynamicSharedMemorySize, STEP_SMEM);
        smem_set = 1;
    }

    // one prep launch: all splits + bias + init
    prep_w2<<<dim3(16, 64, 4), 256>>>(W_cell, W_hid, embed, b_cell);

    // E' = embed @ Wx + b (bf16 3-pass tensor cores), M=1024 N=4096 K=512
    mma_gemm<<<dim3(32, 8), NTHR, STEP_SMEM>>>(0, nullptr, nullptr);

    // 128 LSTM CTAs + 16 images-projection CTAs, all co-resident
    lstm_persist<<<dim3(36, 4), NTHR, STEP_SMEM>>>(message, images, W_img, b_img, out);

    // hidden projection: h_final @ W_hid + b (bf16 3-pass), M=512 N=1024 K=1024
    mma_gemm<<<dim3(8, 4), NTHR, STEP_SMEM>>>(1, b_hid, out + (size_t)B_SZ * HID);
}

// round 17
// speedup vs baseline: 1.0317x; 1.0035x over previous
#include <cuda_runtime.h>
#include <cuda_bf16.h>
#include <math.h>
#include <stdint.h>

#define B_SZ   512
#define T_SZ   128
#define HID    1024
#define EMB    512
#define GATES  4096
#define WK     1024      // recurrent K (h only)
#define NCH    16        // chunks of 64 K-elems
#define NTHR   1024

// ---------------- device scratch (allocation-free) ----------------
__device__ __nv_bfloat16 g_Whi[GATES * WK];      // [p][k'] permuted N-major (h part)
__device__ __nv_bfloat16 g_Wlo[GATES * WK];
__device__ __nv_bfloat16 g_Xhi[GATES * EMB];     // [p][k] permuted N-major (x part)
__device__ __nv_bfloat16 g_Xlo[GATES * EMB];
__device__ __nv_bfloat16 g_Hhi[HID * WK];        // W_hid split, N-major [n][k]
__device__ __nv_bfloat16 g_Hlo[HID * WK];
__device__ __nv_bfloat16 g_Ehi[1024 * EMB];      // embed split, [v][k]
__device__ __nv_bfloat16 g_Elo[1024 * EMB];
__device__ float g_bp[GATES];                    // permuted bias (+1 on f)
__device__ float g_Ep[1024 * GATES];             // E'[vocab][p]
__device__ __nv_bfloat16 g_hbhi[2][B_SZ * HID];  // double-buffered h (bf16 hi/lo)
__device__ __nv_bfloat16 g_hblo[2][B_SZ * HID];
__device__ float g_pp[B_SZ * HID];               // split-K partial for hidden proj
__device__ unsigned g_bar[128];                  // 4 m-group barriers, stride 32
__device__ unsigned g_bar2;                      // split-K reduce barrier

// ---------------- helpers ----------------
__device__ __forceinline__ uint32_t smem_u32(const void* p) {
    uint32_t r;
    asm("{ .reg .u64 t; cvta.to.shared.u64 t, %1; cvt.u32.u64 %0, t; }" : "=r"(r) : "l"(p));
    return r;
}
__device__ __forceinline__ void cpa16(uint32_t dst, const void* src) {
    asm volatile("cp.async.cg.shared.global [%0], [%1], 16;" :: "r"(dst), "l"(src) : "memory");
}
#define CP_COMMIT() asm volatile("cp.async.commit_group;" ::: "memory")
#define CP_WAIT1()  asm volatile("cp.async.wait_group 1;" ::: "memory")
#define CP_WAIT0()  asm volatile("cp.async.wait_group 0;" ::: "memory")

#define LDMX4(r, addr) \
    asm volatile("ldmatrix.sync.aligned.m8n8.x4.shared.b16 {%0,%1,%2,%3}, [%4];" \
        : "=r"((r)[0]), "=r"((r)[1]), "=r"((r)[2]), "=r"((r)[3]) : "r"(addr))

#define MMA(acc, a, b0, b1) \
    asm volatile("mma.sync.aligned.m16n8k16.row.col.f32.bf16.bf16.f32 " \
        "{%0,%1,%2,%3}, {%4,%5,%6,%7}, {%8,%9}, {%0,%1,%2,%3};" \
        : "+f"((acc)[0]), "+f"((acc)[1]), "+f"((acc)[2]), "+f"((acc)[3]) \
        : "r"((a)[0]), "r"((a)[1]), "r"((a)[2]), "r"((a)[3]), "r"(b0), "r"(b1))

#define SW(o) ((uint32_t)(o) ^ ((((uint32_t)(o)) >> 3) & 0x70))

__device__ __forceinline__ float sigm(float x) { return 1.0f / (1.0f + __expf(-x)); }
__device__ __forceinline__ float tanh_f(float x) {
    float e = __expf(2.0f * x);
    return 1.0f - 2.0f / (e + 1.0f);
}

// smem: 3 stages; each stage = 4 regions (Ahi/Alo/Bhi/Blo) of 128 rows x 128B.
#define OFF_AHI   0
#define OFF_ALO   16384
#define OFF_BHI   32768
#define OFF_BLO   49152
#define STAGE_SZ  65536
#define STEP_SMEM (3 * STAGE_SZ)   // 196608

#define PREF_A(base, kb) do { \
    cpa16((base) + OFF_AHI + sw0, aHhi + (kb) + go0); \
    cpa16((base) + OFF_ALO + sw0, aHlo + (kb) + go0); \
} while (0)
#define PREF_B(base, kb) do { \
    cpa16((base) + OFF_BHI + sw0, bWhi + (kb) + go0); \
    cpa16((base) + OFF_BLO + sw0, bWlo + (kb) + go0); \
} while (0)

// ---------------- in-kernel images projection (16 extra CTAs) ----------------
__device__ void proj_images(char* smem, const float* __restrict__ A,
                            const float* __restrict__ W, const float* __restrict__ bias,
                            float* __restrict__ C, int pm, int pn, int tid)
{
    const int K = 2048, N = 1024;
    float (*As)[16][132] = (float(*)[16][132])smem;
    float (*Bs)[16][256] = (float(*)[16][256])(smem + 18432);

    const int ar = tid >> 3, ak = (tid & 7) * 2;
    const int br = tid >> 6, bc = (tid & 63) * 4;
    const int tm = (tid >> 5) * 4, tn = (tid & 31) * 8;

    const float* aP = A + (size_t)(pm + ar) * K + ak;
    const float* bP = W + (size_t)br * N + pn + bc;

    float acc[4][8];
    #pragma unroll
    for (int i = 0; i < 4; i++)
        #pragma unroll
        for (int j = 0; j < 8; j++) acc[i][j] = 0.0f;

    {
        const float2 va = *(const float2*)aP;
        const float4 vb = *(const float4*)bP;
        As[0][ak][ar] = va.x; As[0][ak + 1][ar] = va.y;
        *(float4*)&Bs[0][br][bc] = vb;
    }
    __syncthreads();

    int buf = 0;
    for (int k0 = 16; k0 <= K; k0 += 16) {
        const bool more = (k0 < K);
        float2 nva; float4 nvb;
        if (more) {
            nva = *(const float2*)(aP + k0);
            nvb = *(const float4*)(bP + (size_t)k0 * N);
        }
        #pragma unroll
        for (int kk = 0; kk < 16; kk++) {
            float a[4], b[8];
            *(float4*)&a[0] = *(const float4*)&As[buf][kk][tm];
            *(float4*)&b[0] = *(const float4*)&Bs[buf][kk][tn];
            *(float4*)&b[4] = *(const float4*)&Bs[buf][kk][tn + 4];
            #pragma unroll
            for (int i = 0; i < 4; i++)
                #pragma unroll
                for (int j = 0; j < 8; j++)
                    acc[i][j] = fmaf(a[i], b[j], acc[i][j]);
        }
        if (more) {
            const int nb = buf ^ 1;
            As[nb][ak][ar] = nva.x; As[nb][ak + 1][ar] = nva.y;
            *(float4*)&Bs[nb][br][bc] = nvb;
        }
        __syncthreads();
        buf ^= 1;
    }

    float bia[8];
    *(float4*)&bia[0] = *(const float4*)(bias + pn + tn);
    *(float4*)&bia[4] = *(const float4*)(bias + pn + tn + 4);
    #pragma unroll
    for (int i = 0; i < 4; i++) {
        float4 o0, o1;
        o0.x = acc[i][0] + bia[0]; o0.y = acc[i][1] + bia[1];
        o0.z = acc[i][2] + bia[2]; o0.w = acc[i][3] + bia[3];
        o1.x = acc[i][4] + bia[4]; o1.y = acc[i][5] + bia[5];
        o1.z = acc[i][6] + bia[6]; o1.w = acc[i][7] + bia[7];
        float* crow_ = C + (size_t)(pm + tm + i) * N + pn + tn;
        *(float4*)(crow_)     = o0;
        *(float4*)(crow_ + 4) = o1;
    }
}

// ========== persistent LSTM (all 128 steps) + overlapped images projection ==========
__global__ void __launch_bounds__(NTHR, 1)
lstm_persist(const int* __restrict__ message,
             const float* __restrict__ images, const float* __restrict__ W_img,
             const float* __restrict__ b_img, float* __restrict__ out)
{
    extern __shared__ __align__(1024) char smem[];
    const int tid = threadIdx.x;

    if (blockIdx.x >= 32) {
        const int id = (blockIdx.x - 32) * 4 + blockIdx.y;
        proj_images(smem, images, W_img, b_img, out,
                    (id >> 2) * 128, (id & 3) * 256, tid);
        return;
    }

    const uint32_t sm = smem_u32(smem);
    const int lane = tid & 31;
    const int wid  = tid >> 5;
    const int bx   = blockIdx.x;
    const int bm   = blockIdx.y * 128;

    const int r = tid >> 3;
    const int q = tid & 7;
    const char* bWhi = (const char*)(g_Whi + (size_t)(bx * 128 + r) * WK);
    const char* bWlo = (const char*)(g_Wlo + (size_t)(bx * 128 + r) * WK);
    const char* hHi[2] = { (const char*)(g_hbhi[0] + (size_t)(bm + r) * HID),
                           (const char*)(g_hbhi[1] + (size_t)(bm + r) * HID) };
    const char* hLo[2] = { (const char*)(g_hblo[0] + (size_t)(bm + r) * HID),
                           (const char*)(g_hblo[1] + (size_t)(bm + r) * HID) };
    const uint32_t sw0 = SW(r * 128 + q * 16);
    const int go0 = q * 16;

    const int wm = (wid >> 3) * 32;
    const int wn = (wid & 7) * 16;
    const int aRow = (lane & 15);
    const int aSel = ((lane >> 4) & 1) * 16;
    const int bRowBase = (lane & 7) + ((lane >> 4) & 1) * 8;
    const int bSel = ((lane >> 3) & 1) * 16;

    const int erow  = bm + (tid >> 3);
    const int esub  = tid & 7;
    const int* msgp = message + erow * T_SZ;
    float* smC = (float*)(smem + STAGE_SZ);

    float4 creg = make_float4(0.0f, 0.0f, 0.0f, 0.0f);

    PREF_B(sm, 0);
    PREF_B(sm + 2 * STAGE_SZ, 2 * 128);

    #pragma unroll 1
    for (int t = 0; t < T_SZ; t++) {
        const int msg = msgp[t];
        const char* aHhi = hHi[t & 1];
        const char* aHlo = hLo[t & 1];

        float acc[2][2][4];
        #pragma unroll
        for (int i = 0; i < 2; i++)
            #pragma unroll
            for (int j = 0; j < 2; j++)
                #pragma unroll
                for (int k = 0; k < 4; k++) acc[i][j][k] = 0.0f;

        PREF_A(sm, 0);
        CP_COMMIT();
        PREF_A(sm + STAGE_SZ, 128);
        PREF_B(sm + STAGE_SZ, 128);
        CP_COMMIT();

        int sc = 0, sp = 2;
        #pragma unroll 1
        for (int c = 0; c < NCH; c++) {
            if (c < NCH - 1) { CP_WAIT1(); } else { CP_WAIT0(); }
            __syncthreads();

            if (c + 2 < NCH) {
                const uint32_t dst = sm + sp * STAGE_SZ;
                const int kb = (c + 2) * 128;
                PREF_A(dst, kb);
                if (c != 0) PREF_B(dst, kb);
                CP_COMMIT();
            }

            const uint32_t stage = sm + sc * STAGE_SZ;
            #pragma unroll
            for (int k16 = 0; k16 < 4; k16++) {
                const int kb = k16 * 32;
                uint32_t ah[2][4], al[2][4], bh[4], bl[4];
                #pragma unroll
                for (int mi = 0; mi < 2; mi++) {
                    const uint32_t ao = SW((wm + mi * 16 + aRow) * 128 + kb + aSel);
                    LDMX4(ah[mi], stage + OFF_AHI + ao);
                    LDMX4(al[mi], stage + OFF_ALO + ao);
                }
                {
                    const uint32_t bo = SW((wn + bRowBase) * 128 + kb + bSel);
                    LDMX4(bh, stage + OFF_BHI + bo);
                    LDMX4(bl, stage + OFF_BLO + bo);
                }
                #pragma unroll
                for (int mi = 0; mi < 2; mi++) {
                    #pragma unroll
                    for (int n8 = 0; n8 < 2; n8++) {
                        const uint32_t bh0 = bh[n8 * 2], bh1 = bh[n8 * 2 + 1];
                        const uint32_t bl0 = bl[n8 * 2], bl1 = bl[n8 * 2 + 1];
                        MMA(acc[mi][n8], ah[mi], bh0, bh1);
                        MMA(acc[mi][n8], al[mi], bh0, bh1);
                        MMA(acc[mi][n8], ah[mi], bl0, bl1);
                    }
                }
            }
            sc = (sc == 2) ? 0 : sc + 1;
            sp = (sp == 2) ? 0 : sp + 1;
        }

        __syncthreads();

        if (t + 1 < T_SZ) {
            PREF_B(sm, 0);
            PREF_B(sm + 2 * STAGE_SZ, 2 * 128);
        }

        #pragma unroll
        for (int mi = 0; mi < 2; mi++) {
            #pragma unroll
            for (int n8 = 0; n8 < 2; n8++) {
                const int row = wm + mi * 16 + (lane >> 2);
                const int col = wn + n8 * 8 + (lane & 3) * 2;
                smC[row * 132 + col]           = acc[mi][n8][0];
                smC[row * 132 + col + 1]       = acc[mi][n8][1];
                smC[(row + 8) * 132 + col]     = acc[mi][n8][2];
                smC[(row + 8) * 132 + col + 1] = acc[mi][n8][3];
            }
        }
        __syncthreads();

        {
            const float* cr = smC + (tid >> 3) * 132 + esub * 4;
            const float* ep = g_Ep + (size_t)msg * GATES + bx * 128 + esub * 4;
            __nv_bfloat16* hh = g_hbhi[(t + 1) & 1] + (size_t)erow * HID + bx * 32 + esub * 4;
            __nv_bfloat16* hl = g_hblo[(t + 1) & 1] + (size_t)erow * HID + bx * 32 + esub * 4;
            float* cv = (float*)&creg;
            __nv_bfloat16 hhb[4], hlb[4];
            #pragma unroll
            for (int l = 0; l < 4; l++) {
                const float iv = cr[l]      + ep[l];
                const float gv = cr[32 + l] + ep[32 + l];
                const float fv = cr[64 + l] + ep[64 + l];
                const float ov = cr[96 + l] + ep[96 + l];
                const float cc = sigm(fv) * cv[l] + sigm(iv) * tanh_f(gv);
                const float hv = sigm(ov) * tanh_f(cc);
                cv[l] = cc;
                const __nv_bfloat16 hi = __float2bfloat16(hv);
                hhb[l] = hi;
                hlb[l] = __float2bfloat16(hv - __bfloat162float(hi));
            }
            *(int2*)hh = *(int2*)hhb;
            *(int2*)hl = *(int2*)hlb;
        }

        if (t + 1 < T_SZ) {
            __threadfence();
            __syncthreads();
            if (tid == 0) {
                unsigned* bar = g_bar + (blockIdx.y << 5);
                atomicAdd(bar, 1u);
                const unsigned target = 32u * (unsigned)(t + 1);
                while (*(volatile unsigned*)bar < target) { __nanosleep(64); }
            }
            __syncthreads();
        }
    }
}

// ====== generic bf16 3-pass MMA GEMM ======
// mode 0: E' = embedsplit @ Xsplit(permuted) + g_bp -> g_Ep ; grid (32,8), K=512
// mode 1: proj = h_final @ Hsplit + bias ; grid (8,8) split-K=2 with
//         deterministic two-phase reduce (kh=1 -> g_pp, kh=0 combines)
__global__ void __launch_bounds__(NTHR, 1)
mma_gemm(int mode, const float* __restrict__ bias_ext, float* __restrict__ c_ext)
{
    extern __shared__ __align__(1024) char smem[];
    const uint32_t sm = smem_u32(smem);
    const int tid  = threadIdx.x;
    const int lane = tid & 31;
    const int wid  = tid >> 5;
    const int bx   = blockIdx.x;
    int bm, kh = 0;
    if (mode) { bm = (blockIdx.y & 3) * 128; kh = blockIdx.y >> 2; }
    else      { bm = blockIdx.y * 128; }

    const int nch = 8;   // K=512 per CTA in both modes
    const int r = tid >> 3;
    const int q = tid & 7;
    const char *aHhi, *aHlo, *bWhi, *bWlo;
    if (mode) {
        const size_t koff = (size_t)kh * 1024;   // 512 bf16 = 1024 bytes
        aHhi = (const char*)g_hbhi[0] + (size_t)(bm + r) * 2048 + koff;
        aHlo = (const char*)g_hblo[0] + (size_t)(bm + r) * 2048 + koff;
        bWhi = (const char*)g_Hhi + (size_t)(bx * 128 + r) * 2048 + koff;
        bWlo = (const char*)g_Hlo + (size_t)(bx * 128 + r) * 2048 + koff;
    } else {
        aHhi = (const char*)g_Ehi + (size_t)(bm + r) * 1024;
        aHlo = (const char*)g_Elo + (size_t)(bm + r) * 1024;
        bWhi = (const char*)g_Xhi + (size_t)(bx * 128 + r) * 1024;
        bWlo = (const char*)g_Xlo + (size_t)(bx * 128 + r) * 1024;
    }
    const uint32_t sw0 = SW(r * 128 + q * 16);
    const int go0 = q * 16;

    const int wm = (wid >> 3) * 32;
    const int wn = (wid & 7) * 16;
    const int aRow = (lane & 15);
    const int aSel = ((lane >> 4) & 1) * 16;
    const int bRowBase = (lane & 7) + ((lane >> 4) & 1) * 8;
    const int bSel = ((lane >> 3) & 1) * 16;
    float* smC = (float*)(smem + STAGE_SZ);

    float acc[2][2][4];
    #pragma unroll
    for (int i = 0; i < 2; i++)
        #pragma unroll
        for (int j = 0; j < 2; j++)
            #pragma unroll
            for (int k = 0; k < 4; k++) acc[i][j][k] = 0.0f;

    PREF_A(sm, 0); PREF_B(sm, 0);
    CP_COMMIT();
    PREF_A(sm + STAGE_SZ, 128); PREF_B(sm + STAGE_SZ, 128);
    CP_COMMIT();

    int sc = 0, sp = 2;
    #pragma unroll 1
    for (int c = 0; c < nch; c++) {
        if (c < nch - 1) { CP_WAIT1(); } else { CP_WAIT0(); }
        __syncthreads();

        if (c + 2 < nch) {
            const uint32_t dst = sm + sp * STAGE_SZ;
            const int kb = (c + 2) * 128;
            PREF_A(dst, kb); PREF_B(dst, kb);
            CP_COMMIT();
        }

        const uint32_t stage = sm + sc * STAGE_SZ;
        #pragma unroll
        for (int k16 = 0; k16 < 4; k16++) {
            const int kb = k16 * 32;
            uint32_t ah[2][4], al[2][4], bh[4], bl[4];
            #pragma unroll
            for (int mi = 0; mi < 2; mi++) {
                const uint32_t ao = SW((wm + mi * 16 + aRow) * 128 + kb + aSel);
                LDMX4(ah[mi], stage + OFF_AHI + ao);
                LDMX4(al[mi], stage + OFF_ALO + ao);
            }
            {
                const uint32_t bo = SW((wn + bRowBase) * 128 + kb + bSel);
                LDMX4(bh, stage + OFF_BHI + bo);
                LDMX4(bl, stage + OFF_BLO + bo);
            }
            #pragma unroll
            for (int mi = 0; mi < 2; mi++) {
                #pragma unroll
                for (int n8 = 0; n8 < 2; n8++) {
                    const uint32_t bh0 = bh[n8 * 2], bh1 = bh[n8 * 2 + 1];
                    const uint32_t bl0 = bl[n8 * 2], bl1 = bl[n8 * 2 + 1];
                    MMA(acc[mi][n8], ah[mi], bh0, bh1);
                    MMA(acc[mi][n8], al[mi], bh0, bh1);
                    MMA(acc[mi][n8], ah[mi], bl0, bl1);
                }
            }
        }
        sc = (sc == 2) ? 0 : sc + 1;
        sp = (sp == 2) ? 0 : sp + 1;
    }

    __syncthreads();
    #pragma unroll
    for (int mi = 0; mi < 2; mi++) {
        #pragma unroll
        for (int n8 = 0; n8 < 2; n8++) {
            const int row = wm + mi * 16 + (lane >> 2);
            const int col = wn + n8 * 8 + (lane & 3) * 2;
            smC[row * 132 + col]           = acc[mi][n8][0];
            smC[row * 132 + col + 1]       = acc[mi][n8][1];
            smC[(row + 8) * 132 + col]     = acc[mi][n8][2];
            smC[(row + 8) * 132 + col + 1] = acc[mi][n8][3];
        }
    }
    __syncthreads();

    const int row = tid >> 3;
    const int e = tid & 7;
    const int gcol = bx * 128 + e * 16;
    const float* cr = smC + row * 132 + e * 16;

    if (mode == 0) {
        float* op = g_Ep + (size_t)(bm + row) * GATES + gcol;
        #pragma unroll
        for (int j = 0; j < 4; j++) {
            float4 v = *(const float4*)(cr + j * 4);
            const float4 b = *(const float4*)(g_bp + gcol + j * 4);
            v.x += b.x; v.y += b.y; v.z += b.z; v.w += b.w;
            *(float4*)(op + j * 4) = v;
        }
    } else if (kh == 1) {
        // phase 1: store K[512:1024) partial, signal
        float* pp = g_pp + (size_t)(bm + row) * 1024 + gcol;
        #pragma unroll
        for (int j = 0; j < 4; j++)
            *(float4*)(pp + j * 4) = *(const float4*)(cr + j * 4);
        __threadfence();
        __syncthreads();
        if (tid == 0) atomicAdd(&g_bar2, 1u);
    } else {
        // phase 2: wait for all 32 kh=1 CTAs, then out = own + partial + bias
        if (tid == 0) {
            while (*(volatile unsigned*)&g_bar2 < 32u) { __nanosleep(128); }
        }
        __syncthreads();
        const float* pp = g_pp + (size_t)(bm + row) * 1024 + gcol;
        float* op = c_ext + (size_t)(bm + row) * 1024 + gcol;
        #pragma unroll
        for (int j = 0; j < 4; j++) {
            float4 v = *(const float4*)(cr + j * 4);
            const float4 p = *(const float4*)(pp + j * 4);
            const float4 b = *(const float4*)(bias_ext + gcol + j * 4);
            v.x += p.x + b.x; v.y += p.y + b.y;
            v.z += p.z + b.z; v.w += p.w + b.w;
            *(float4*)(op + j * 4) = v;
        }
    }
}

// ====== prep: all splits/transposes + bias + init, one launch ======
__global__ __launch_bounds__(256)
void prep_w2(const float* __restrict__ Wc, const float* __restrict__ Wh,
             const float* __restrict__ Emb, const float* __restrict__ b_cell)
{
    const int tid = threadIdx.x;
    const int z = blockIdx.z;

    if (z == 2) {
        const int blk = blockIdx.y * 16 + blockIdx.x;
        const int base = blk * 512 + tid * 2;
        {
            const float2 v = *(const float2*)(Emb + base);
            const __nv_bfloat16 h0 = __float2bfloat16(v.x);
            const __nv_bfloat16 h1 = __float2bfloat16(v.y);
            g_Ehi[base]     = h0;
            g_Ehi[base + 1] = h1;
            g_Elo[base]     = __float2bfloat16(v.x - __bfloat162float(h0));
            g_Elo[base + 1] = __float2bfloat16(v.y - __bfloat162float(h1));
            const __nv_bfloat16 zb = __float2bfloat16(0.0f);
            g_hbhi[0][base] = zb; g_hbhi[0][base + 1] = zb;
            g_hblo[0][base] = zb; g_hblo[0][base + 1] = zb;
        }
        if (blk < 16) {
            const int p = blk * 256 + tid;
            const int j = p >> 7, qg = (p >> 5) & 3, l = p & 31;
            const int n = qg * 1024 + j * 32 + l;
            g_bp[p] = b_cell[n] + (qg == 2 ? 1.0f : 0.0f);
        }
        if (blk == 0 && tid < 128) g_bar[tid] = 0u;
        if (blk == 0 && tid == 128) g_bar2 = 0u;
        return;
    }

    __shared__ float tile[64][65];
    if (z == 1 && blockIdx.x >= 8) return;
    if (z == 3 && (blockIdx.x >= 16 || blockIdx.y >= 16)) return;

    const int k0 = blockIdx.x * 64;
    const int n0 = blockIdx.y * 64;
    const float* src = (z == 3) ? Wh : Wc;
    const int srcN   = (z == 3) ? 1024 : GATES;
    const int row0   = (z == 0) ? EMB : 0;

    const int lr = tid >> 2;
    const int lc = (tid & 3) * 16;
    #pragma unroll
    for (int i = 0; i < 4; i++) {
        const float4 v = *(const float4*)(src + (size_t)(row0 + k0 + lr) * srcN + n0 + lc + i * 4);
        tile[lr][lc + i * 4 + 0] = v.x;
        tile[lr][lc + i * 4 + 1] = v.y;
        tile[lr][lc + i * 4 + 2] = v.z;
        tile[lr][lc + i * 4 + 3] = v.w;
    }
    __syncthreads();

    const int pl = tid >> 2;
    const int kq = (tid & 3) * 16;
    const int n = n0 + pl;
    int p;
    if (z == 3) {
        p = n;
    } else {
        const int qg = n >> 10, j = (n >> 5) & 31, l = n & 31;
        p = j * 128 + qg * 32 + l;
    }
    const int kstride = (z == 1) ? EMB : WK;
    __nv_bfloat16* dhi = (z == 0 ? g_Whi : (z == 1 ? g_Xhi : g_Hhi)) + (size_t)p * kstride + k0 + kq;
    __nv_bfloat16* dlo = (z == 0 ? g_Wlo : (z == 1 ? g_Xlo : g_Hlo)) + (size_t)p * kstride + k0 + kq;
    __nv_bfloat16 hb[16], lb[16];
    #pragma unroll
    for (int i = 0; i < 16; i++) {
        const float w = tile[kq + i][pl];
        const __nv_bfloat16 hi = __float2bfloat16(w);
        hb[i] = hi;
        lb[i] = __float2bfloat16(w - __bfloat162float(hi));
    }
    *(int4*)dhi = *(int4*)hb; *(int4*)(dhi + 8) = *(int4*)(hb + 8);
    *(int4*)dlo = *(int4*)lb; *(int4*)(dlo + 8) = *(int4*)(lb + 8);
}

// ================= launch =================
extern "C" void kernel_launch(void* const* d_in, const int* in_sizes, int n_in,
                              void* d_out, int out_size)
{
    const float* images  = (const float*)d_in[0];
    const float* embed   = (const float*)d_in[1];
    const float* W_cell  = (const float*)d_in[2];
    const float* b_cell  = (const float*)d_in[3];
    const float* W_img   = (const float*)d_in[4];
    const float* b_img   = (const float*)d_in[5];
    const float* W_hid   = (const float*)d_in[6];
    const float* b_hid   = (const float*)d_in[7];
    const int*   message = (const int*)d_in[8];
    float* out = (float*)d_out;
    (void)in_sizes; (void)n_in; (void)out_size;

    static int smem_set = 0;
    if (!smem_set) {
        cudaFuncSetAttribute(lstm_persist, cudaFuncAttributeMaxDynamicSharedMemorySize, STEP_SMEM);
        cudaFuncSetAttribute(mma_gemm, cudaFuncAttributeMaxDynamicSharedMemorySize, STEP_SMEM);
        smem_set = 1;
    }

    // one prep launch: all splits + bias + init
    prep_w2<<<dim3(16, 64, 4), 256>>>(W_cell, W_hid, embed, b_cell);

    // E' = embed @ Wx + b (bf16 3-pass tensor cores), M=1024 N=4096 K=512
    mma_gemm<<<dim3(32, 8), NTHR, STEP_SMEM>>>(0, nullptr, nullptr);

    // 128 LSTM CTAs + 16 images-projection CTAs, all co-resident
    lstm_persist<<<dim3(36, 4), NTHR, STEP_SMEM>>>(message, images, W_img, b_img, out);

    // hidden projection: split-K=2 (64 CTAs), deterministic two-phase reduce
    mma_gemm<<<dim3(8, 8), NTHR, STEP_SMEM>>>(1, b_hid, out + (size_t)B_SZ * HID);
}